// round 6
// baseline (speedup 1.0000x reference)
#include <cuda_runtime.h>
#include <cuda_fp16.h>
#include <math.h>

#define Bn 32
#define Ln 2048
#define Dn 1024
#define Un 512

#define TM 128
#define TN 64
#define KC 32            // halfs per k-chunk (64 B rows)
#define NST 4
#define NSTAGES (Dn / KC)   // 32

// static device scratch (no runtime allocation)
__device__ __align__(16) __half g_valsh[(size_t)Bn * Ln * Dn];  // fp16 values
__device__ __align__(16) __half g_wvTh[Un * Dn];                // fp16 Wv^T [u][k]
__device__ float g_ubias[Bn * Un];
__device__ float g_score[Bn * Ln];

__device__ __forceinline__ float tanh_fast(float x) {
    float y;
    asm("tanh.approx.f32 %0, %1;" : "=f"(y) : "f"(x));
    return y;
}
__device__ __forceinline__ int swz(int r) { return (r ^ (r >> 2)) & 3; }

__device__ __forceinline__ void ldsm4(unsigned addr, unsigned& r0, unsigned& r1,
                                      unsigned& r2, unsigned& r3) {
    asm volatile("ldmatrix.sync.aligned.m8n8.x4.shared.b16 {%0,%1,%2,%3}, [%4];"
                 : "=r"(r0), "=r"(r1), "=r"(r2), "=r"(r3) : "r"(addr));
}

// ---------------------------------------------------------------------------
// Convert: values -> fp16 (rn), 8 elems/thread; Wv -> transposed fp16 [u][k]
// ---------------------------------------------------------------------------
__global__ void convert_values_kernel(const float4* __restrict__ src) {
    size_t i = (size_t)blockIdx.x * blockDim.x + threadIdx.x;
    float4 a = src[2 * i], b = src[2 * i + 1];
    union { uint4 u; __half2 h[4]; } o;
    o.h[0] = __floats2half2_rn(a.x, a.y);
    o.h[1] = __floats2half2_rn(a.z, a.w);
    o.h[2] = __floats2half2_rn(b.x, b.y);
    o.h[3] = __floats2half2_rn(b.z, b.w);
    reinterpret_cast<uint4*>(g_valsh)[i] = o.u;
}
__global__ void convert_wv_kernel(const float* __restrict__ Wv) {
    int i = blockIdx.x * blockDim.x + threadIdx.x;  // i = u*1024 + k
    int u = i >> 10, k = i & 1023;
    g_wvTh[i] = __float2half_rn(Wv[k * Un + u]);
}

// ---------------------------------------------------------------------------
// Per-batch prep (q@Wh + fused l-independent bias terms)
// ---------------------------------------------------------------------------
__global__ void prep_kernel(const float* __restrict__ query,
                            const float* __restrict__ mask,
                            const int*   __restrict__ tstep,
                            const float* __restrict__ Wh,
                            const float* __restrict__ bh,
                            const float* __restrict__ bv,
                            const float* __restrict__ Wp,
                            const float* __restrict__ bp,
                            const float* __restrict__ bm)
{
    int b = blockIdx.x;
    int tid = threadIdx.x;                 // 512 threads
    __shared__ float qs[Dn];
    __shared__ float red[512];
    __shared__ float s_loglen, s_logts;

    float cnt = 0.f;
    for (int l = tid; l < Ln; l += 512)
        cnt += (mask[b * Ln + l] == 0.0f) ? 1.0f : 0.0f;
    red[tid] = cnt;
    __syncthreads();
    for (int s = 256; s > 0; s >>= 1) {
        if (tid < s) red[tid] += red[tid + s];
        __syncthreads();
    }
    if (tid == 0) {
        s_loglen = logf(1.0f + red[0]);
        int iv = tstep[0];
        float ts;
        if (iv >= 0 && iv < 1000000) ts = (float)iv;
        else ts = __int_as_float(iv);
        s_logts = logf(1.0f + ts);
    }
    for (int d = tid; d < Dn; d += 512) qs[d] = query[b * Dn + d];
    __syncthreads();

    int u = tid;
    float acc = 0.f;
#pragma unroll 8
    for (int d = 0; d < Dn; d++) acc += qs[d] * Wh[d * Un + u];
    g_ubias[b * Un + u] = acc + bh[u] + bv[u] + bp[u] + bm[u]
                        + s_logts * Wp[u] + s_loglen * Wp[2 * Un + u];
}

// ---------------------------------------------------------------------------
// Score init (vb + mask penalty), zero context output region
// ---------------------------------------------------------------------------
__global__ void init_kernel(const float* __restrict__ mask,
                            const float* __restrict__ vb,
                            float* __restrict__ out)
{
    int i = blockIdx.x * blockDim.x + threadIdx.x;
    if (i < Bn * Ln) g_score[i] = vb[0] + mask[i] * -1e9f;
    if (i < Bn * Dn) out[i] = 0.0f;
}

// ---------------------------------------------------------------------------
// Fused score GEMM: fp16 MMA with f16 accumulation promoted to f32 every K=64.
//   256 thr = 8 warps (2M x 4N); warp tile 64x16; TM=128, TN=64
// ---------------------------------------------------------------------------
__global__ __launch_bounds__(256, 2) void score_kernel(
    const float* __restrict__ Wp,
    const float* __restrict__ Wm,
    const float* __restrict__ vw,
    const float* __restrict__ prev)
{
    extern __shared__ char smraw[];
    __half* As = (__half*)smraw;                       // NST*TM*KC halfs (32KB)
    __half* Bs = As + NST * TM * KC;                   // NST*TN*KC halfs (16KB)
    float*  eb = (float*)(Bs + NST * TN * KC);         // 8*TN floats
    float*  prevs = eb + 8 * TN;                       // TM+4
    unsigned As_u = (unsigned)__cvta_generic_to_shared(As);
    unsigned Bs_u = (unsigned)__cvta_generic_to_shared(Bs);

    int utile = blockIdx.x, ltile = blockIdx.y, bb = blockIdx.z;
    int l0 = ltile * TM, u0 = utile * TN;
    int tid = threadIdx.x, lane = tid & 31, warp = tid >> 5;
    int warpM = warp >> 2, warpN = warp & 3;
    int qa = lane & 3, rr = lane >> 2;

    const __half* abase = g_valsh + (size_t)bb * Ln * Dn + (size_t)l0 * Dn;
    const __half* bbase = g_wvTh + (size_t)u0 * Dn;

    // epilogue staging (visible via in-loop barriers)
    if (tid < TN) {
        eb[tid]          = g_ubias[bb * Un + u0 + tid];
        eb[TN + tid]     = Wp[Un + u0 + tid];
        eb[2 * TN + tid] = vw[u0 + tid];
#pragma unroll
        for (int j = 0; j < 5; j++) eb[(3 + j) * TN + tid] = Wm[j * Un + u0 + tid];
    }
    if (tid < TM + 4) {
        int gl = l0 - 2 + tid;
        prevs[tid] = (gl >= 0 && gl < Ln) ? prev[bb * Ln + gl] : 0.0f;
    }

    // ldmatrix per-lane byte offsets within a stage buffer (kk=0; kk=1 = ^32)
    int lr = lane & 7, grp = lane >> 3;
    int rowadd = lr + 8 * (grp & 1);
    int cbase = grp >> 1;
    unsigned aoffb[4], boffb;
#pragma unroll
    for (int mt = 0; mt < 4; mt++) {
        int row = warpM * 64 + mt * 16 + rowadd;
        aoffb[mt] = row * 64 + 16 * (cbase ^ swz(row));
    }
    {
        int row = warpN * 16 + rowadd;
        boffb = row * 64 + 16 * (cbase ^ swz(row));
    }

    float acc[4][2][4];
#pragma unroll
    for (int a = 0; a < 4; a++)
#pragma unroll
        for (int n = 0; n < 2; n++)
#pragma unroll
            for (int c = 0; c < 4; c++) acc[a][n][c] = 0.f;
    unsigned cf[4][2][2];
#pragma unroll
    for (int a = 0; a < 4; a++)
#pragma unroll
        for (int n = 0; n < 2; n++) { cf[a][n][0] = 0u; cf[a][n][1] = 0u; }

    auto issue_stage = [&](int s) {
        int soA = (s % NST) * (TM * KC);
        int soB = (s % NST) * (TN * KC);
        const __half* ab = abase + s * KC;
        const __half* bsrc = bbase + s * KC;
#pragma unroll
        for (int i = 0; i < 2; i++) {
            int p = tid + 256 * i;
            int r = p >> 2, c = p & 3;
            unsigned da = (unsigned)__cvta_generic_to_shared(
                &As[soA + r * KC + 8 * (c ^ swz(r))]);
            asm volatile("cp.async.cg.shared.global [%0], [%1], 16;"
                         ::"r"(da), "l"(ab + (size_t)r * Dn + 8 * c));
        }
        {
            int r = tid >> 2, c = tid & 3;   // 64 rows x 4 chunks
            unsigned db = (unsigned)__cvta_generic_to_shared(
                &Bs[soB + r * KC + 8 * (c ^ swz(r))]);
            asm volatile("cp.async.cg.shared.global [%0], [%1], 16;"
                         ::"r"(db), "l"(bsrc + (size_t)r * Dn + 8 * c));
        }
    };

    issue_stage(0);
    asm volatile("cp.async.commit_group;");
    issue_stage(1);
    asm volatile("cp.async.commit_group;");
    issue_stage(2);
    asm volatile("cp.async.commit_group;");

    for (int s = 0; s < NSTAGES; s++) {
        asm volatile("cp.async.wait_group 2;");
        __syncthreads();
        if (s + 3 < NSTAGES) issue_stage(s + 3);
        asm volatile("cp.async.commit_group;");

        unsigned Abuf = As_u + (unsigned)((s % NST) * (TM * KC) * 2);
        unsigned Bbuf = Bs_u + (unsigned)((s % NST) * (TN * KC) * 2);
#pragma unroll
        for (int kk = 0; kk < 2; kk++) {
            unsigned x = kk ? 32u : 0u;
            unsigned af[4][4], bf[4];
#pragma unroll
            for (int mt = 0; mt < 4; mt++)
                ldsm4(Abuf + (aoffb[mt] ^ x),
                      af[mt][0], af[mt][1], af[mt][2], af[mt][3]);
            ldsm4(Bbuf + (boffb ^ x), bf[0], bf[1], bf[2], bf[3]);
#pragma unroll
            for (int nt = 0; nt < 2; nt++) {
                unsigned b0 = bf[nt], b1 = bf[nt + 2];
#pragma unroll
                for (int mt = 0; mt < 4; mt++) {
                    asm volatile(
                        "mma.sync.aligned.m16n8k16.row.col.f16.f16.f16.f16 "
                        "{%0,%1}, {%2,%3,%4,%5}, {%6,%7}, {%0,%1};"
                        : "+r"(cf[mt][nt][0]), "+r"(cf[mt][nt][1])
                        : "r"(af[mt][0]), "r"(af[mt][1]), "r"(af[mt][2]),
                          "r"(af[mt][3]), "r"(b0), "r"(b1));
                }
            }
        }
        if (s & 1) {   // promote f16 partials (K=64 span) into f32
#pragma unroll
            for (int mt = 0; mt < 4; mt++)
#pragma unroll
                for (int nt = 0; nt < 2; nt++) {
                    float2 p0 = __half22float2(
                        *reinterpret_cast<__half2*>(&cf[mt][nt][0]));
                    float2 p1 = __half22float2(
                        *reinterpret_cast<__half2*>(&cf[mt][nt][1]));
                    acc[mt][nt][0] += p0.x;
                    acc[mt][nt][1] += p0.y;
                    acc[mt][nt][2] += p1.x;
                    acc[mt][nt][3] += p1.y;
                    cf[mt][nt][0] = 0u;
                    cf[mt][nt][1] = 0u;
                }
        }
    }

    // ---- epilogue ----
#pragma unroll
    for (int mt = 0; mt < 4; mt++) {
#pragma unroll
        for (int half = 0; half < 2; half++) {
            int rl = warpM * 64 + mt * 16 + rr + 8 * half;
            float ll = logf(2.0f + (float)(l0 + rl));
            float sumv = 0.f;
#pragma unroll
            for (int nt = 0; nt < 2; nt++) {
#pragma unroll
                for (int j = 0; j < 2; j++) {
                    int col = warpN * 16 + nt * 8 + qa * 2 + j;
                    float sc = acc[mt][nt][half * 2 + j] + eb[col] + ll * eb[TN + col];
#pragma unroll
                    for (int w = 0; w < 5; w++)
                        sc += prevs[rl + w] * eb[(3 + w) * TN + col];
                    sumv += tanh_fast(sc) * eb[2 * TN + col];
                }
            }
            sumv += __shfl_xor_sync(0xffffffffu, sumv, 1);
            sumv += __shfl_xor_sync(0xffffffffu, sumv, 2);
            if (qa == 0) atomicAdd(&g_score[bb * Ln + l0 + rl], sumv);
        }
    }
}

// ---------------------------------------------------------------------------
// Softmax over L per batch -> attention weights into d_out
// ---------------------------------------------------------------------------
__global__ void softmax_kernel(float* __restrict__ out)
{
    int b = blockIdx.x;
    int tid = threadIdx.x;   // 256
    __shared__ float red[256];
    __shared__ float s_max, s_inv;

    float m = -1e30f;
    for (int l = tid; l < Ln; l += 256) m = fmaxf(m, g_score[b * Ln + l]);
    red[tid] = m;
    __syncthreads();
    for (int s = 128; s > 0; s >>= 1) {
        if (tid < s) red[tid] = fmaxf(red[tid], red[tid + s]);
        __syncthreads();
    }
    if (tid == 0) s_max = red[0];
    __syncthreads();

    float sum = 0.f;
    for (int l = tid; l < Ln; l += 256) sum += expf(g_score[b * Ln + l] - s_max);
    red[tid] = sum;
    __syncthreads();
    for (int s = 128; s > 0; s >>= 1) {
        if (tid < s) red[tid] += red[tid + s];
        __syncthreads();
    }
    if (tid == 0) s_inv = 1.0f / red[0];
    __syncthreads();

    float* attn = out + Bn * Dn;
    for (int l = tid; l < Ln; l += 256)
        attn[b * Ln + l] = expf(g_score[b * Ln + l] - s_max) * s_inv;
}

// ---------------------------------------------------------------------------
// context[b,d] = sum_l attn[b,l] * values_h[b,l,d]   (half2 path)
// ---------------------------------------------------------------------------
__global__ __launch_bounds__(512) void context_kernel(float* __restrict__ out)
{
    int lc = blockIdx.x;    // 16 chunks of 128 rows
    int b  = blockIdx.y;    // 32
    int d2 = threadIdx.x;   // 512 half2 cols
    const float* attn = out + Bn * Dn + b * Ln + lc * 128;
    const __half2* v = reinterpret_cast<const __half2*>(g_valsh)
                     + ((size_t)b * Ln + (size_t)lc * 128) * (Dn / 2) + d2;
    float ax = 0.f, ay = 0.f;
#pragma unroll 4
    for (int l = 0; l < 128; l++) {
        float2 f = __half22float2(v[(size_t)l * (Dn / 2)]);
        float w = __ldg(&attn[l]);
        ax += w * f.x;
        ay += w * f.y;
    }
    atomicAdd(&out[b * Dn + 2 * d2], ax);
    atomicAdd(&out[b * Dn + 2 * d2 + 1], ay);
}

// ---------------------------------------------------------------------------
extern "C" void kernel_launch(void* const* d_in, const int* in_sizes, int n_in,
                              void* d_out, int out_size)
{
    const float* query = (const float*)d_in[0];
    const float* values = (const float*)d_in[1];
    const float* mask = (const float*)d_in[2];
    const float* prev = (const float*)d_in[3];
    const int*   tstep = (const int*)d_in[4];
    const float* Wh = (const float*)d_in[5];
    const float* bh = (const float*)d_in[6];
    const float* Wv = (const float*)d_in[7];
    const float* bv = (const float*)d_in[8];
    const float* Wp = (const float*)d_in[9];
    const float* bp = (const float*)d_in[10];
    const float* Wm = (const float*)d_in[11];
    const float* bm = (const float*)d_in[12];
    const float* vw = (const float*)d_in[13];
    const float* vb = (const float*)d_in[14];
    float* out = (float*)d_out;

    const int smem_bytes = (NST * TM * KC + NST * TN * KC) * 2
                         + (8 * TN + TM + 8) * 4;
    cudaFuncSetAttribute(score_kernel,
                         cudaFuncAttributeMaxDynamicSharedMemorySize, smem_bytes);

    convert_values_kernel<<<((size_t)Bn * Ln * Dn / 8) / 256, 256>>>((const float4*)values);
    convert_wv_kernel<<<(Un * Dn) / 256, 256>>>(Wv);
    prep_kernel<<<Bn, 512>>>(query, mask, tstep, Wh, bh, bv, Wp, bp, bm);
    init_kernel<<<(Bn * Ln + 255) / 256, 256>>>(mask, vb, out);
    dim3 gs(Un / TN, Ln / TM, Bn);
    score_kernel<<<gs, 256, smem_bytes>>>(Wp, Wm, vw, prev);
    softmax_kernel<<<Bn, 256>>>(out);
    context_kernel<<<dim3(16, Bn), 512>>>(out);
}

// round 7
// speedup vs baseline: 1.1161x; 1.1161x over previous
#include <cuda_runtime.h>
#include <cuda_fp16.h>
#include <math.h>

#define Bn 32
#define Ln 2048
#define Dn 1024
#define Un 512

#define TM 128
#define TN 128
#define KC 32            // halfs per k-chunk (64 B rows)
#define NST 4
#define NSTAGES (Dn / KC)   // 32

// static device scratch (no runtime allocation)
__device__ __align__(16) __half g_valsh[(size_t)Bn * Ln * Dn];  // fp16 values
__device__ __align__(16) __half g_wvTh[Un * Dn];                // fp16 Wv^T [u][k]
__device__ float g_ubias[Bn * Un];
__device__ float g_score[Bn * Ln];

__device__ __forceinline__ float tanh_fast(float x) {
    float y;
    asm("tanh.approx.f32 %0, %1;" : "=f"(y) : "f"(x));
    return y;
}
__device__ __forceinline__ int swz(int r) { return (r ^ (r >> 2)) & 3; }

__device__ __forceinline__ void ldsm4(unsigned addr, unsigned& r0, unsigned& r1,
                                      unsigned& r2, unsigned& r3) {
    asm volatile("ldmatrix.sync.aligned.m8n8.x4.shared.b16 {%0,%1,%2,%3}, [%4];"
                 : "=r"(r0), "=r"(r1), "=r"(r2), "=r"(r3) : "r"(addr));
}

// ---------------------------------------------------------------------------
// Launch 0: values -> fp16 (rn), 8 elems/thread
// ---------------------------------------------------------------------------
__global__ void convert_values_kernel(const float4* __restrict__ src) {
    size_t i = (size_t)blockIdx.x * blockDim.x + threadIdx.x;
    float4 a = src[2 * i], b = src[2 * i + 1];
    union { uint4 u; __half2 h[4]; } o;
    o.h[0] = __floats2half2_rn(a.x, a.y);
    o.h[1] = __floats2half2_rn(a.z, a.w);
    o.h[2] = __floats2half2_rn(b.x, b.y);
    o.h[3] = __floats2half2_rn(b.z, b.w);
    reinterpret_cast<uint4*>(g_valsh)[i] = o.u;
}

// ---------------------------------------------------------------------------
// Launch 1 (fused misc): Wv -> transposed fp16 [u][k]; g_score init; out zero
// ---------------------------------------------------------------------------
__global__ void misc_kernel(const float* __restrict__ Wv,
                            const float* __restrict__ mask,
                            const float* __restrict__ vb,
                            float* __restrict__ out)
{
    int i = blockIdx.x * blockDim.x + threadIdx.x;
    if (i < Un * Dn) {
        int u = i >> 10, k = i & 1023;
        g_wvTh[i] = __float2half_rn(Wv[k * Un + u]);
    }
    if (i < Bn * Ln) g_score[i] = vb[0] + mask[i] * -1e9f;
    if (i < Bn * Dn) out[i] = 0.0f;
}

// ---------------------------------------------------------------------------
// Launch 2: per-batch prep (q@Wh + fused l-independent bias terms)
// ---------------------------------------------------------------------------
__global__ void prep_kernel(const float* __restrict__ query,
                            const float* __restrict__ mask,
                            const int*   __restrict__ tstep,
                            const float* __restrict__ Wh,
                            const float* __restrict__ bh,
                            const float* __restrict__ bv,
                            const float* __restrict__ Wp,
                            const float* __restrict__ bp,
                            const float* __restrict__ bm)
{
    int b = blockIdx.x;
    int tid = threadIdx.x;                 // 512 threads
    __shared__ float qs[Dn];
    __shared__ float red[512];
    __shared__ float s_loglen, s_logts;

    float cnt = 0.f;
    for (int l = tid; l < Ln; l += 512)
        cnt += (mask[b * Ln + l] == 0.0f) ? 1.0f : 0.0f;
    red[tid] = cnt;
    __syncthreads();
    for (int s = 256; s > 0; s >>= 1) {
        if (tid < s) red[tid] += red[tid + s];
        __syncthreads();
    }
    if (tid == 0) {
        s_loglen = __logf(1.0f + red[0]);
        int iv = tstep[0];
        float ts;
        if (iv >= 0 && iv < 1000000) ts = (float)iv;
        else ts = __int_as_float(iv);
        s_logts = __logf(1.0f + ts);
    }
    for (int d = tid; d < Dn; d += 512) qs[d] = query[b * Dn + d];
    __syncthreads();

    int u = tid;
    float acc = 0.f;
#pragma unroll 8
    for (int d = 0; d < Dn; d++) acc += qs[d] * Wh[d * Un + u];
    g_ubias[b * Un + u] = acc + bh[u] + bv[u] + bp[u] + bm[u]
                        + s_logts * Wp[u] + s_loglen * Wp[2 * Un + u];
}

// ---------------------------------------------------------------------------
// Launch 3 (profiled): fused score GEMM, fp16 m16n8k16, ldmatrix, 4-stage
//   256 thr = 8 warps (2M x 4N); warp tile 64x32; TM=128, TN=128
// ---------------------------------------------------------------------------
__global__ __launch_bounds__(256, 2) void score_kernel(
    const float* __restrict__ Wp,
    const float* __restrict__ Wm,
    const float* __restrict__ vw,
    const float* __restrict__ prev)
{
    extern __shared__ char smraw[];
    __half* As = (__half*)smraw;                       // NST*TM*KC halfs (32KB)
    __half* Bs = As + NST * TM * KC;                   // NST*TN*KC halfs (32KB)
    float*  eb = (float*)(Bs + NST * TN * KC);         // 8*TN floats
    float*  prevs = eb + 8 * TN;                       // TM+4
    unsigned As_u = (unsigned)__cvta_generic_to_shared(As);
    unsigned Bs_u = (unsigned)__cvta_generic_to_shared(Bs);

    int utile = blockIdx.x, ltile = blockIdx.y, bb = blockIdx.z;
    int l0 = ltile * TM, u0 = utile * TN;
    int tid = threadIdx.x, lane = tid & 31, warp = tid >> 5;
    int warpM = warp >> 2, warpN = warp & 3;
    int qa = lane & 3, rr = lane >> 2;

    const __half* abase = g_valsh + (size_t)bb * Ln * Dn + (size_t)l0 * Dn;
    const __half* bbase = g_wvTh + (size_t)u0 * Dn;

    auto issue_stage = [&](int s) {
        int so = (s % NST) * (TM * KC);
        const __half* ab = abase + s * KC;
        const __half* bsrc = bbase + s * KC;
#pragma unroll
        for (int i = 0; i < 2; i++) {
            int p = tid + 256 * i;
            int r = p >> 2, c = p & 3;
            unsigned da = (unsigned)__cvta_generic_to_shared(
                &As[so + r * KC + 8 * (c ^ swz(r))]);
            asm volatile("cp.async.cg.shared.global [%0], [%1], 16;"
                         ::"r"(da), "l"(ab + (size_t)r * Dn + 8 * c));
            unsigned db = (unsigned)__cvta_generic_to_shared(
                &Bs[so + r * KC + 8 * (c ^ swz(r))]);
            asm volatile("cp.async.cg.shared.global [%0], [%1], 16;"
                         ::"r"(db), "l"(bsrc + (size_t)r * Dn + 8 * c));
        }
    };

    issue_stage(0);
    asm volatile("cp.async.commit_group;");
    issue_stage(1);
    asm volatile("cp.async.commit_group;");
    issue_stage(2);
    asm volatile("cp.async.commit_group;");

    // epilogue staging — after prologue so it overlaps the first cp.asyncs
    if (tid < TN) {
        eb[tid]          = g_ubias[bb * Un + u0 + tid];
        eb[TN + tid]     = Wp[Un + u0 + tid];
        eb[2 * TN + tid] = vw[u0 + tid];
#pragma unroll
        for (int j = 0; j < 5; j++) eb[(3 + j) * TN + tid] = Wm[j * Un + u0 + tid];
    }
    if (tid < TM + 4) {
        int gl = l0 - 2 + tid;
        prevs[tid] = (gl >= 0 && gl < Ln) ? prev[bb * Ln + gl] : 0.0f;
    }

    // ldmatrix per-lane byte offsets within a stage buffer (kk=0; kk=1 = ^32)
    int lr = lane & 7, grp = lane >> 3;
    int rowadd = lr + 8 * (grp & 1);
    int cbase = grp >> 1;
    unsigned aoffb[4], boffb[2];
#pragma unroll
    for (int mt = 0; mt < 4; mt++) {
        int row = warpM * 64 + mt * 16 + rowadd;
        aoffb[mt] = row * 64 + 16 * (cbase ^ swz(row));
    }
#pragma unroll
    for (int ntp = 0; ntp < 2; ntp++) {
        int row = warpN * 32 + ntp * 16 + rowadd;
        boffb[ntp] = row * 64 + 16 * (cbase ^ swz(row));
    }

    float acc[4][4][4];
#pragma unroll
    for (int a = 0; a < 4; a++)
#pragma unroll
        for (int n = 0; n < 4; n++)
#pragma unroll
            for (int c = 0; c < 4; c++) acc[a][n][c] = 0.f;

    for (int s = 0; s < NSTAGES; s++) {
        asm volatile("cp.async.wait_group 2;");
        __syncthreads();
        if (s + 3 < NSTAGES) issue_stage(s + 3);
        asm volatile("cp.async.commit_group;");

        unsigned Abuf = As_u + (unsigned)((s % NST) * (TM * KC) * 2);
        unsigned Bbuf = Bs_u + (unsigned)((s % NST) * (TN * KC) * 2);
#pragma unroll
        for (int kk = 0; kk < 2; kk++) {
            unsigned x = kk ? 32u : 0u;
            unsigned af[4][4], bf[2][4];
#pragma unroll
            for (int mt = 0; mt < 4; mt++)
                ldsm4(Abuf + (aoffb[mt] ^ x),
                      af[mt][0], af[mt][1], af[mt][2], af[mt][3]);
#pragma unroll
            for (int ntp = 0; ntp < 2; ntp++)
                ldsm4(Bbuf + (boffb[ntp] ^ x),
                      bf[ntp][0], bf[ntp][1], bf[ntp][2], bf[ntp][3]);
#pragma unroll
            for (int nt = 0; nt < 4; nt++) {
                unsigned b0 = bf[nt >> 1][nt & 1];
                unsigned b1 = bf[nt >> 1][(nt & 1) + 2];
#pragma unroll
                for (int mt = 0; mt < 4; mt++) {
                    asm volatile(
                        "mma.sync.aligned.m16n8k16.row.col.f32.f16.f16.f32 "
                        "{%0,%1,%2,%3}, {%4,%5,%6,%7}, {%8,%9}, {%0,%1,%2,%3};"
                        : "+f"(acc[mt][nt][0]), "+f"(acc[mt][nt][1]),
                          "+f"(acc[mt][nt][2]), "+f"(acc[mt][nt][3])
                        : "r"(af[mt][0]), "r"(af[mt][1]), "r"(af[mt][2]), "r"(af[mt][3]),
                          "r"(b0), "r"(b1));
                }
            }
        }
    }

    // ---- epilogue ----
#pragma unroll
    for (int mt = 0; mt < 4; mt++) {
#pragma unroll
        for (int half = 0; half < 2; half++) {
            int rl = warpM * 64 + mt * 16 + rr + 8 * half;
            float ll = __logf(2.0f + (float)(l0 + rl));
            float sumv = 0.f;
#pragma unroll
            for (int nt = 0; nt < 4; nt++) {
#pragma unroll
                for (int j = 0; j < 2; j++) {
                    int col = warpN * 32 + nt * 8 + qa * 2 + j;
                    float sc = acc[mt][nt][half * 2 + j] + eb[col] + ll * eb[TN + col];
#pragma unroll
                    for (int w = 0; w < 5; w++)
                        sc += prevs[rl + w] * eb[(3 + w) * TN + col];
                    sumv += tanh_fast(sc) * eb[2 * TN + col];
                }
            }
            sumv += __shfl_xor_sync(0xffffffffu, sumv, 1);
            sumv += __shfl_xor_sync(0xffffffffu, sumv, 2);
            if (qa == 0) atomicAdd(&g_score[bb * Ln + l0 + rl], sumv);
        }
    }
}

// ---------------------------------------------------------------------------
// Launch 4: softmax over L per batch -> attention weights into d_out
// ---------------------------------------------------------------------------
__global__ void softmax_kernel(float* __restrict__ out)
{
    int b = blockIdx.x;
    int tid = threadIdx.x;   // 256
    __shared__ float red[256];
    __shared__ float s_max, s_inv;

    float m = -1e30f;
    for (int l = tid; l < Ln; l += 256) m = fmaxf(m, g_score[b * Ln + l]);
    red[tid] = m;
    __syncthreads();
    for (int s = 128; s > 0; s >>= 1) {
        if (tid < s) red[tid] = fmaxf(red[tid], red[tid + s]);
        __syncthreads();
    }
    if (tid == 0) s_max = red[0];
    __syncthreads();

    float sum = 0.f;
    for (int l = tid; l < Ln; l += 256) sum += expf(g_score[b * Ln + l] - s_max);
    red[tid] = sum;
    __syncthreads();
    for (int s = 128; s > 0; s >>= 1) {
        if (tid < s) red[tid] += red[tid + s];
        __syncthreads();
    }
    if (tid == 0) s_inv = 1.0f / red[0];
    __syncthreads();

    float* attn = out + Bn * Dn;
    for (int l = tid; l < Ln; l += 256)
        attn[b * Ln + l] = expf(g_score[b * Ln + l] - s_max) * s_inv;
}

// ---------------------------------------------------------------------------
// Launch 5: context[b,d] = sum_l attn[b,l] * values_h[b,l,d]   (half2 path)
// ---------------------------------------------------------------------------
__global__ __launch_bounds__(512) void context_kernel(float* __restrict__ out)
{
    int lc = blockIdx.x;    // 16 chunks of 128 rows
    int b  = blockIdx.y;    // 32
    int d2 = threadIdx.x;   // 512 half2 cols
    const float* attn = out + Bn * Dn + b * Ln + lc * 128;
    const __half2* v = reinterpret_cast<const __half2*>(g_valsh)
                     + ((size_t)b * Ln + (size_t)lc * 128) * (Dn / 2) + d2;
    float ax = 0.f, ay = 0.f;
#pragma unroll 4
    for (int l = 0; l < 128; l++) {
        float2 f = __half22float2(v[(size_t)l * (Dn / 2)]);
        float w = __ldg(&attn[l]);
        ax += w * f.x;
        ay += w * f.y;
    }
    atomicAdd(&out[b * Dn + 2 * d2], ax);
    atomicAdd(&out[b * Dn + 2 * d2 + 1], ay);
}

// ---------------------------------------------------------------------------
extern "C" void kernel_launch(void* const* d_in, const int* in_sizes, int n_in,
                              void* d_out, int out_size)
{
    const float* query = (const float*)d_in[0];
    const float* values = (const float*)d_in[1];
    const float* mask = (const float*)d_in[2];
    const float* prev = (const float*)d_in[3];
    const int*   tstep = (const int*)d_in[4];
    const float* Wh = (const float*)d_in[5];
    const float* bh = (const float*)d_in[6];
    const float* Wv = (const float*)d_in[7];
    const float* bv = (const float*)d_in[8];
    const float* Wp = (const float*)d_in[9];
    const float* bp = (const float*)d_in[10];
    const float* Wm = (const float*)d_in[11];
    const float* bm = (const float*)d_in[12];
    const float* vw = (const float*)d_in[13];
    const float* vb = (const float*)d_in[14];
    float* out = (float*)d_out;

    const int smem_bytes = (NST * TM * KC + NST * TN * KC) * 2
                         + (8 * TN + TM + 8) * 4;
    cudaFuncSetAttribute(score_kernel,
                         cudaFuncAttributeMaxDynamicSharedMemorySize, smem_bytes);

    convert_values_kernel<<<((size_t)Bn * Ln * Dn / 8) / 256, 256>>>((const float4*)values);
    misc_kernel<<<(Un * Dn + 255) / 256, 256>>>(Wv, mask, vb, out);
    prep_kernel<<<Bn, 512>>>(query, mask, tstep, Wh, bh, bv, Wp, bp, bm);
    dim3 gs(Un / TN, Ln / TM, Bn);
    score_kernel<<<gs, 256, smem_bytes>>>(Wp, Wm, vw, prev);
    softmax_kernel<<<Bn, 256>>>(out);
    context_kernel<<<dim3(16, Bn), 512>>>(out);
}

// round 9
// speedup vs baseline: 1.1263x; 1.0091x over previous
#include <cuda_runtime.h>
#include <cuda_fp16.h>
#include <math.h>

#define Bn 32
#define Ln 2048
#define Dn 1024
#define Un 512

#define TM 128
#define TN 128
#define KC 32            // halfs per k-chunk (64 B rows)
#define NST 4
#define NSTAGES (Dn / KC)   // 32

// static device scratch (no runtime allocation)
__device__ __align__(16) __half g_valsh[(size_t)Bn * Ln * Dn];  // fp16 values
__device__ __align__(16) __half g_wvTh[Un * Dn];                // fp16 Wv^T [u][k]
__device__ float g_ubias[Bn * Un];
__device__ float g_score[Bn * Ln];

__device__ __forceinline__ float tanh_fast(float x) {
    float y;
    asm("tanh.approx.f32 %0, %1;" : "=f"(y) : "f"(x));
    return y;
}
__device__ __forceinline__ int swz(int r) { return (r ^ (r >> 2)) & 3; }

__device__ __forceinline__ void ldsm4(unsigned addr, unsigned& r0, unsigned& r1,
                                      unsigned& r2, unsigned& r3) {
    asm volatile("ldmatrix.sync.aligned.m8n8.x4.shared.b16 {%0,%1,%2,%3}, [%4];"
                 : "=r"(r0), "=r"(r1), "=r"(r2), "=r"(r3) : "r"(addr));
}

// ---------------------------------------------------------------------------
// Launch 0: values -> fp16 (rn), 8 elems/thread
// ---------------------------------------------------------------------------
__global__ void convert_values_kernel(const float4* __restrict__ src) {
    size_t i = (size_t)blockIdx.x * blockDim.x + threadIdx.x;
    float4 a = src[2 * i], b = src[2 * i + 1];
    union { uint4 u; __half2 h[4]; } o;
    o.h[0] = __floats2half2_rn(a.x, a.y);
    o.h[1] = __floats2half2_rn(a.z, a.w);
    o.h[2] = __floats2half2_rn(b.x, b.y);
    o.h[3] = __floats2half2_rn(b.z, b.w);
    reinterpret_cast<uint4*>(g_valsh)[i] = o.u;
}

// ---------------------------------------------------------------------------
// Launch 1 (fused misc): Wv -> transposed fp16 [u][k]; g_score init; out zero
// ---------------------------------------------------------------------------
__global__ void misc_kernel(const float* __restrict__ Wv,
                            const float* __restrict__ mask,
                            const float* __restrict__ vb,
                            float* __restrict__ out)
{
    int i = blockIdx.x * blockDim.x + threadIdx.x;
    if (i < Un * Dn) {
        int u = i >> 10, k = i & 1023;
        g_wvTh[i] = __float2half_rn(Wv[k * Un + u]);
    }
    if (i < Bn * Ln) g_score[i] = vb[0] + mask[i] * -1e9f;
    if (i < Bn * Dn) out[i] = 0.0f;
}

// ---------------------------------------------------------------------------
// Launch 2: per-batch prep (q@Wh + fused l-independent bias terms)
// ---------------------------------------------------------------------------
__global__ void prep_kernel(const float* __restrict__ query,
                            const float* __restrict__ mask,
                            const int*   __restrict__ tstep,
                            const float* __restrict__ Wh,
                            const float* __restrict__ bh,
                            const float* __restrict__ bv,
                            const float* __restrict__ Wp,
                            const float* __restrict__ bp,
                            const float* __restrict__ bm)
{
    int b = blockIdx.x;
    int tid = threadIdx.x;                 // 512 threads
    __shared__ float qs[Dn];
    __shared__ float red[512];
    __shared__ float s_loglen, s_logts;

    float cnt = 0.f;
    for (int l = tid; l < Ln; l += 512)
        cnt += (mask[b * Ln + l] == 0.0f) ? 1.0f : 0.0f;
    red[tid] = cnt;
    __syncthreads();
    for (int s = 256; s > 0; s >>= 1) {
        if (tid < s) red[tid] += red[tid + s];
        __syncthreads();
    }
    if (tid == 0) {
        s_loglen = __logf(1.0f + red[0]);
        int iv = tstep[0];
        float ts;
        if (iv >= 0 && iv < 1000000) ts = (float)iv;
        else ts = __int_as_float(iv);
        s_logts = __logf(1.0f + ts);
    }
    for (int d = tid; d < Dn; d += 512) qs[d] = query[b * Dn + d];
    __syncthreads();

    int u = tid;
    float acc = 0.f;
#pragma unroll 8
    for (int d = 0; d < Dn; d++) acc += qs[d] * Wh[d * Un + u];
    g_ubias[b * Un + u] = acc + bh[u] + bv[u] + bp[u] + bm[u]
                        + s_logts * Wp[u] + s_loglen * Wp[2 * Un + u];
}

// ---------------------------------------------------------------------------
// Launch 3 (profiled): fused score GEMM, fp16 m16n8k16, ldmatrix, 4-stage
//   Stage body: ALL fragment LDSMs first, then 32 back-to-back MMAs.
//   256 thr = 8 warps (2M x 4N); warp tile 64x32; TM=128, TN=128
// ---------------------------------------------------------------------------
__global__ __launch_bounds__(256, 2) void score_kernel(
    const float* __restrict__ Wp,
    const float* __restrict__ Wm,
    const float* __restrict__ vw,
    const float* __restrict__ prev)
{
    extern __shared__ char smraw[];
    __half* As = (__half*)smraw;                       // NST*TM*KC halfs (32KB)
    __half* Bs = As + NST * TM * KC;                   // NST*TN*KC halfs (32KB)
    float*  eb = (float*)(Bs + NST * TN * KC);         // 8*TN floats
    float*  prevs = eb + 8 * TN;                       // TM+4
    unsigned As_u = (unsigned)__cvta_generic_to_shared(As);
    unsigned Bs_u = (unsigned)__cvta_generic_to_shared(Bs);

    int utile = blockIdx.x, ltile = blockIdx.y, bb = blockIdx.z;
    int l0 = ltile * TM, u0 = utile * TN;
    int tid = threadIdx.x, lane = tid & 31, warp = tid >> 5;
    int warpM = warp >> 2, warpN = warp & 3;
    int qa = lane & 3, rr = lane >> 2;

    const __half* abase = g_valsh + (size_t)bb * Ln * Dn + (size_t)l0 * Dn;
    const __half* bbase = g_wvTh + (size_t)u0 * Dn;

    // precomputed cp.async addressing (constant across stages except buffer id)
    int cr = tid >> 2, cc = tid & 3;
    unsigned dstA0 = (unsigned)(cr * KC + 8 * (cc ^ swz(cr))) * 2;
    unsigned dstA1 = (unsigned)((cr + 64) * KC + 8 * (cc ^ swz(cr + 64))) * 2;
    size_t srcOff0 = (size_t)cr * Dn + 8 * cc;
    size_t srcOff1 = (size_t)(cr + 64) * Dn + 8 * cc;

    auto issue_stage = [&](int s) {
        unsigned so = (unsigned)((s & 3) * (TM * KC) * 2);
        const __half* ab = abase + s * KC;
        const __half* bsrc = bbase + s * KC;
        asm volatile("cp.async.cg.shared.global [%0], [%1], 16;"
                     ::"r"(As_u + so + dstA0), "l"(ab + srcOff0));
        asm volatile("cp.async.cg.shared.global [%0], [%1], 16;"
                     ::"r"(As_u + so + dstA1), "l"(ab + srcOff1));
        asm volatile("cp.async.cg.shared.global [%0], [%1], 16;"
                     ::"r"(Bs_u + so + dstA0), "l"(bsrc + srcOff0));
        asm volatile("cp.async.cg.shared.global [%0], [%1], 16;"
                     ::"r"(Bs_u + so + dstA1), "l"(bsrc + srcOff1));
    };

    issue_stage(0);
    asm volatile("cp.async.commit_group;");
    issue_stage(1);
    asm volatile("cp.async.commit_group;");
    issue_stage(2);
    asm volatile("cp.async.commit_group;");

    // epilogue staging — after prologue so it overlaps the first cp.asyncs
    if (tid < TN) {
        eb[tid]          = g_ubias[bb * Un + u0 + tid];
        eb[TN + tid]     = Wp[Un + u0 + tid];
        eb[2 * TN + tid] = vw[u0 + tid];
#pragma unroll
        for (int j = 0; j < 5; j++) eb[(3 + j) * TN + tid] = Wm[j * Un + u0 + tid];
    }
    if (tid < TM + 4) {
        int gl = l0 - 2 + tid;
        prevs[tid] = (gl >= 0 && gl < Ln) ? prev[bb * Ln + gl] : 0.0f;
    }

    // ldmatrix per-lane byte offsets within a stage buffer (kk=0; kk=1 = ^32)
    int lr = lane & 7, grp = lane >> 3;
    int rowadd = lr + 8 * (grp & 1);
    int cbase = grp >> 1;
    unsigned aoffb[4], boffb[2];
#pragma unroll
    for (int mt = 0; mt < 4; mt++) {
        int row = warpM * 64 + mt * 16 + rowadd;
        aoffb[mt] = row * 64 + 16 * (cbase ^ swz(row));
    }
#pragma unroll
    for (int ntp = 0; ntp < 2; ntp++) {
        int row = warpN * 32 + ntp * 16 + rowadd;
        boffb[ntp] = row * 64 + 16 * (cbase ^ swz(row));
    }

    float acc[4][4][4];
#pragma unroll
    for (int a = 0; a < 4; a++)
#pragma unroll
        for (int n = 0; n < 4; n++)
#pragma unroll
            for (int c = 0; c < 4; c++) acc[a][n][c] = 0.f;

    for (int s = 0; s < NSTAGES; s++) {
        asm volatile("cp.async.wait_group 2;");
        __syncthreads();
        if (s + 3 < NSTAGES) issue_stage(s + 3);
        asm volatile("cp.async.commit_group;");

        unsigned Abuf = As_u + (unsigned)((s & 3) * (TM * KC) * 2);
        unsigned Bbuf = Bs_u + (unsigned)((s & 3) * (TN * KC) * 2);

        // ---- load ALL fragments for this stage (12 LDSM), no MMA deps ----
        unsigned af[2][4][4], bf[2][2][4];
#pragma unroll
        for (int kk = 0; kk < 2; kk++) {
            unsigned x = kk ? 32u : 0u;
#pragma unroll
            for (int ntp = 0; ntp < 2; ntp++)
                ldsm4(Bbuf + (boffb[ntp] ^ x),
                      bf[kk][ntp][0], bf[kk][ntp][1], bf[kk][ntp][2], bf[kk][ntp][3]);
#pragma unroll
            for (int mt = 0; mt < 4; mt++)
                ldsm4(Abuf + (aoffb[mt] ^ x),
                      af[kk][mt][0], af[kk][mt][1], af[kk][mt][2], af[kk][mt][3]);
        }
        // ---- 32 back-to-back MMAs ----
#pragma unroll
        for (int kk = 0; kk < 2; kk++) {
#pragma unroll
            for (int nt = 0; nt < 4; nt++) {
                unsigned b0 = bf[kk][nt >> 1][nt & 1];
                unsigned b1 = bf[kk][nt >> 1][(nt & 1) + 2];
#pragma unroll
                for (int mt = 0; mt < 4; mt++) {
                    asm volatile(
                        "mma.sync.aligned.m16n8k16.row.col.f32.f16.f16.f32 "
                        "{%0,%1,%2,%3}, {%4,%5,%6,%7}, {%8,%9}, {%0,%1,%2,%3};"
                        : "+f"(acc[mt][nt][0]), "+f"(acc[mt][nt][1]),
                          "+f"(acc[mt][nt][2]), "+f"(acc[mt][nt][3])
                        : "r"(af[kk][mt][0]), "r"(af[kk][mt][1]),
                          "r"(af[kk][mt][2]), "r"(af[kk][mt][3]),
                          "r"(b0), "r"(b1));
                }
            }
        }
    }

    // ---- epilogue ----
#pragma unroll
    for (int mt = 0; mt < 4; mt++) {
#pragma unroll
        for (int half = 0; half < 2; half++) {
            int rl = warpM * 64 + mt * 16 + rr + 8 * half;
            float ll = __logf(2.0f + (float)(l0 + rl));
            float sumv = 0.f;
#pragma unroll
            for (int nt = 0; nt < 4; nt++) {
#pragma unroll
                for (int j = 0; j < 2; j++) {
                    int col = warpN * 32 + nt * 8 + qa * 2 + j;
                    float sc = acc[mt][nt][half * 2 + j] + eb[col] + ll * eb[TN + col];
#pragma unroll
                    for (int w = 0; w < 5; w++)
                        sc += prevs[rl + w] * eb[(3 + w) * TN + col];
                    sumv += tanh_fast(sc) * eb[2 * TN + col];
                }
            }
            sumv += __shfl_xor_sync(0xffffffffu, sumv, 1);
            sumv += __shfl_xor_sync(0xffffffffu, sumv, 2);
            if (qa == 0) atomicAdd(&g_score[bb * Ln + l0 + rl], sumv);
        }
    }
}

// ---------------------------------------------------------------------------
// Launch 4: softmax over L per batch -> attention weights into d_out
// ---------------------------------------------------------------------------
__global__ void softmax_kernel(float* __restrict__ out)
{
    int b = blockIdx.x;
    int tid = threadIdx.x;   // 256
    __shared__ float red[256];
    __shared__ float s_max, s_inv;

    float m = -1e30f;
    for (int l = tid; l < Ln; l += 256) m = fmaxf(m, g_score[b * Ln + l]);
    red[tid] = m;
    __syncthreads();
    for (int s = 128; s > 0; s >>= 1) {
        if (tid < s) red[tid] = fmaxf(red[tid], red[tid + s]);
        __syncthreads();
    }
    if (tid == 0) s_max = red[0];
    __syncthreads();

    float sum = 0.f;
    for (int l = tid; l < Ln; l += 256) sum += expf(g_score[b * Ln + l] - s_max);
    red[tid] = sum;
    __syncthreads();
    for (int s = 128; s > 0; s >>= 1) {
        if (tid < s) red[tid] += red[tid + s];
        __syncthreads();
    }
    if (tid == 0) s_inv = 1.0f / red[0];
    __syncthreads();

    float* attn = out + Bn * Dn;
    for (int l = tid; l < Ln; l += 256)
        attn[b * Ln + l] = expf(g_score[b * Ln + l] - s_max) * s_inv;
}

// ---------------------------------------------------------------------------
// Launch 5: context[b,d] = sum_l attn[b,l] * values_h[b,l,d]   (half2 path)
// ---------------------------------------------------------------------------
__global__ __launch_bounds__(512) void context_kernel(float* __restrict__ out)
{
    int lc = blockIdx.x;    // 16 chunks of 128 rows
    int b  = blockIdx.y;    // 32
    int d2 = threadIdx.x;   // 512 half2 cols
    const float* attn = out + Bn * Dn + b * Ln + lc * 128;
    const __half2* v = reinterpret_cast<const __half2*>(g_valsh)
                     + ((size_t)b * Ln + (size_t)lc * 128) * (Dn / 2) + d2;
    float ax = 0.f, ay = 0.f;
#pragma unroll 4
    for (int l = 0; l < 128; l++) {
        float2 f = __half22float2(v[(size_t)l * (Dn / 2)]);
        float w = __ldg(&attn[l]);
        ax += w * f.x;
        ay += w * f.y;
    }
    atomicAdd(&out[b * Dn + 2 * d2], ax);
    atomicAdd(&out[b * Dn + 2 * d2 + 1], ay);
}

// ---------------------------------------------------------------------------
extern "C" void kernel_launch(void* const* d_in, const int* in_sizes, int n_in,
                              void* d_out, int out_size)
{
    const float* query = (const float*)d_in[0];
    const float* values = (const float*)d_in[1];
    const float* mask = (const float*)d_in[2];
    const float* prev = (const float*)d_in[3];
    const int*   tstep = (const int*)d_in[4];
    const float* Wh = (const float*)d_in[5];
    const float* bh = (const float*)d_in[6];
    const float* Wv = (const float*)d_in[7];
    const float* bv = (const float*)d_in[8];
    const float* Wp = (const float*)d_in[9];
    const float* bp = (const float*)d_in[10];
    const float* Wm = (const float*)d_in[11];
    const float* bm = (const float*)d_in[12];
    const float* vw = (const float*)d_in[13];
    const float* vb = (const float*)d_in[14];
    float* out = (float*)d_out;

    const int smem_bytes = (NST * TM * KC + NST * TN * KC) * 2
                         + (8 * TN + TM + 8) * 4;
    cudaFuncSetAttribute(score_kernel,
                         cudaFuncAttributeMaxDynamicSharedMemorySize, smem_bytes);

    convert_values_kernel<<<((size_t)Bn * Ln * Dn / 8) / 256, 256>>>((const float4*)values);
    misc_kernel<<<(Un * Dn + 255) / 256, 256>>>(Wv, mask, vb, out);
    prep_kernel<<<Bn, 512>>>(query, mask, tstep, Wh, bh, bv, Wp, bp, bm);
    dim3 gs(Un / TN, Ln / TM, Bn);
    score_kernel<<<gs, 256, smem_bytes>>>(Wp, Wm, vw, prev);
    softmax_kernel<<<Bn, 256>>>(out);
    context_kernel<<<dim3(16, Bn), 512>>>(out);
}

// round 10
// speedup vs baseline: 1.1830x; 1.0503x over previous
#include <cuda_runtime.h>
#include <cuda_fp16.h>
#include <math.h>

#define Bn 32
#define Ln 2048
#define Dn 1024
#define Un 512

#define TM 128
#define TN 128
#define KCH 64              // halfs per k-stage (128 B rows)
#define NST 3
#define NSTAGES (Dn / KCH)  // 16
#define STAGE_HALFS (TM * KCH)   // 8192
#define STAGE_BYTES (STAGE_HALFS * 2)  // 16384

// static device scratch (no runtime allocation)
__device__ __align__(16) __half g_valsh[(size_t)Bn * Ln * Dn];  // fp16 values
__device__ __align__(16) __half g_wvTh[Un * Dn];                // fp16 Wv^T [u][k]
__device__ float g_ubias[Bn * Un];
__device__ float g_score[Bn * Ln];
__device__ float g_stat[Bn * 2];

__device__ __forceinline__ float tanh_fast(float x) {
    float y;
    asm("tanh.approx.f32 %0, %1;" : "=f"(y) : "f"(x));
    return y;
}

__device__ __forceinline__ void ldsm4(unsigned addr, unsigned& r0, unsigned& r1,
                                      unsigned& r2, unsigned& r3) {
    asm volatile("ldmatrix.sync.aligned.m8n8.x4.shared.b16 {%0,%1,%2,%3}, [%4];"
                 : "=r"(r0), "=r"(r1), "=r"(r2), "=r"(r3) : "r"(addr));
}

// ---------------------------------------------------------------------------
// Launch 0: values -> fp16 (rn), 8 elems/thread
// ---------------------------------------------------------------------------
__global__ void convert_values_kernel(const float4* __restrict__ src) {
    size_t i = (size_t)blockIdx.x * blockDim.x + threadIdx.x;
    float4 a = src[2 * i], b = src[2 * i + 1];
    union { uint4 u; __half2 h[4]; } o;
    o.h[0] = __floats2half2_rn(a.x, a.y);
    o.h[1] = __floats2half2_rn(a.z, a.w);
    o.h[2] = __floats2half2_rn(b.x, b.y);
    o.h[3] = __floats2half2_rn(b.z, b.w);
    reinterpret_cast<uint4*>(g_valsh)[i] = o.u;
}

// ---------------------------------------------------------------------------
// Launch 1 (fused misc): Wv -> transposed fp16 [u][k]; g_score init;
// zero context output region (atomics target)
// ---------------------------------------------------------------------------
__global__ void misc_kernel(const float* __restrict__ Wv,
                            const float* __restrict__ mask,
                            const float* __restrict__ vb,
                            float* __restrict__ out)
{
    int i = blockIdx.x * blockDim.x + threadIdx.x;
    if (i < Un * Dn) {
        int u = i >> 10, k = i & 1023;
        g_wvTh[i] = __float2half_rn(Wv[k * Un + u]);
    }
    if (i < Bn * Ln) g_score[i] = vb[0] + mask[i] * -1e9f;
    if (i < Bn * Dn) out[i] = 0.0f;
}

// ---------------------------------------------------------------------------
// Launch 2: per-batch prep (q@Wh + fused l-independent bias terms)
// ---------------------------------------------------------------------------
__global__ void prep_kernel(const float* __restrict__ query,
                            const float* __restrict__ mask,
                            const int*   __restrict__ tstep,
                            const float* __restrict__ Wh,
                            const float* __restrict__ bh,
                            const float* __restrict__ bv,
                            const float* __restrict__ Wp,
                            const float* __restrict__ bp,
                            const float* __restrict__ bm)
{
    int b = blockIdx.x;
    int tid = threadIdx.x;                 // 512 threads
    __shared__ float qs[Dn];
    __shared__ float red[512];
    __shared__ float s_loglen, s_logts;

    float cnt = 0.f;
    for (int l = tid; l < Ln; l += 512)
        cnt += (mask[b * Ln + l] == 0.0f) ? 1.0f : 0.0f;
    red[tid] = cnt;
    __syncthreads();
    for (int s = 256; s > 0; s >>= 1) {
        if (tid < s) red[tid] += red[tid + s];
        __syncthreads();
    }
    if (tid == 0) {
        s_loglen = __logf(1.0f + red[0]);
        int iv = tstep[0];
        float ts;
        if (iv >= 0 && iv < 1000000) ts = (float)iv;
        else ts = __int_as_float(iv);
        s_logts = __logf(1.0f + ts);
    }
    for (int d = tid; d < Dn; d += 512) qs[d] = query[b * Dn + d];
    __syncthreads();

    int u = tid;
    float acc = 0.f;
#pragma unroll 8
    for (int d = 0; d < Dn; d++) acc += qs[d] * Wh[d * Un + u];
    g_ubias[b * Un + u] = acc + bh[u] + bv[u] + bp[u] + bm[u]
                        + s_logts * Wp[u] + s_loglen * Wp[2 * Un + u];
}

// ---------------------------------------------------------------------------
// Launch 3 (profiled): fused score GEMM, fp16 m16n8k16, ldmatrix,
//   KCH=64 stages (128B rows, chunk^(row&7) swizzle), NST=3 ring.
//   256 thr = 8 warps (2M x 4N); warp tile 64x32; TM=128, TN=128
// ---------------------------------------------------------------------------
__global__ __launch_bounds__(256, 2) void score_kernel(
    const float* __restrict__ Wp,
    const float* __restrict__ Wm,
    const float* __restrict__ vw,
    const float* __restrict__ prev)
{
    extern __shared__ char smraw[];
    __half* As = (__half*)smraw;                       // NST*16KB
    __half* Bs = As + NST * STAGE_HALFS;               // NST*16KB
    float*  eb = (float*)(Bs + NST * STAGE_HALFS);     // 8*TN floats
    float*  prevs = eb + 8 * TN;                       // TM+4
    unsigned As_u = (unsigned)__cvta_generic_to_shared(As);
    unsigned Bs_u = (unsigned)__cvta_generic_to_shared(Bs);

    int utile = blockIdx.x, ltile = blockIdx.y, bb = blockIdx.z;
    int l0 = ltile * TM, u0 = utile * TN;
    int tid = threadIdx.x, lane = tid & 31, warp = tid >> 5;
    int warpM = warp >> 2, warpN = warp & 3;
    int qa = lane & 3, rr = lane >> 2;

    const __half* abase = g_valsh + (size_t)bb * Ln * Dn + (size_t)l0 * Dn;
    const __half* bbase = g_wvTh + (size_t)u0 * Dn;

    // cp.async addressing: thread covers rows r0+32i, chunk c0 (16B units)
    int r0 = tid >> 3, c0 = tid & 7;
    unsigned dst0 = (unsigned)(r0 * 128 + 16 * (c0 ^ (r0 & 7)));
    size_t src0 = (size_t)r0 * Dn + 8 * c0;

    auto issue_stage = [&](int s) {
        unsigned so = (unsigned)((s % NST) * STAGE_BYTES);
        const __half* ab = abase + s * KCH;
        const __half* bsrc = bbase + s * KCH;
#pragma unroll
        for (int i = 0; i < 4; i++) {
            asm volatile("cp.async.cg.shared.global [%0], [%1], 16;"
                         ::"r"(As_u + so + dst0 + 4096u * i),
                           "l"(ab + src0 + (size_t)32 * i * Dn));
            asm volatile("cp.async.cg.shared.global [%0], [%1], 16;"
                         ::"r"(Bs_u + so + dst0 + 4096u * i),
                           "l"(bsrc + src0 + (size_t)32 * i * Dn));
        }
    };

    issue_stage(0);
    asm volatile("cp.async.commit_group;");
    issue_stage(1);
    asm volatile("cp.async.commit_group;");

    // epilogue staging — overlaps first cp.asyncs
    if (tid < TN) {
        eb[tid]          = g_ubias[bb * Un + u0 + tid];
        eb[TN + tid]     = Wp[Un + u0 + tid];
        eb[2 * TN + tid] = vw[u0 + tid];
#pragma unroll
        for (int j = 0; j < 5; j++) eb[(3 + j) * TN + tid] = Wm[j * Un + u0 + tid];
    }
    if (tid < TM + 4) {
        int gl = l0 - 2 + tid;
        prevs[tid] = (gl >= 0 && gl < Ln) ? prev[bb * Ln + gl] : 0.0f;
    }

    // ldmatrix per-lane byte offsets (kk adds ^ 32*kk)
    int lr = lane & 7, grp = lane >> 3;
    int rowadd = lr + 8 * (grp & 1);
    int cbase = grp >> 1;
    unsigned aoffb[4], boffb[2];
#pragma unroll
    for (int mt = 0; mt < 4; mt++) {
        int row = warpM * 64 + mt * 16 + rowadd;
        aoffb[mt] = row * 128 + 16 * (cbase ^ (row & 7));
    }
#pragma unroll
    for (int ntp = 0; ntp < 2; ntp++) {
        int row = warpN * 32 + ntp * 16 + rowadd;
        boffb[ntp] = row * 128 + 16 * (cbase ^ (row & 7));
    }

    float acc[4][4][4];
#pragma unroll
    for (int a = 0; a < 4; a++)
#pragma unroll
        for (int n = 0; n < 4; n++)
#pragma unroll
            for (int c = 0; c < 4; c++) acc[a][n][c] = 0.f;

#pragma unroll 4
    for (int s = 0; s < NSTAGES; s++) {
        asm volatile("cp.async.wait_group 1;");
        __syncthreads();
        if (s + 2 < NSTAGES) issue_stage(s + 2);
        asm volatile("cp.async.commit_group;");

        unsigned Abuf = As_u + (unsigned)((s % NST) * STAGE_BYTES);
        unsigned Bbuf = Bs_u + (unsigned)((s % NST) * STAGE_BYTES);

#pragma unroll
        for (int h = 0; h < 2; h++) {     // two kk-pairs per stage
            unsigned af[2][4][4], bf[2][2][4];
#pragma unroll
            for (int k2 = 0; k2 < 2; k2++) {
                unsigned x = 32u * (2 * h + k2);
#pragma unroll
                for (int ntp = 0; ntp < 2; ntp++)
                    ldsm4(Bbuf + (boffb[ntp] ^ x),
                          bf[k2][ntp][0], bf[k2][ntp][1],
                          bf[k2][ntp][2], bf[k2][ntp][3]);
#pragma unroll
                for (int mt = 0; mt < 4; mt++)
                    ldsm4(Abuf + (aoffb[mt] ^ x),
                          af[k2][mt][0], af[k2][mt][1],
                          af[k2][mt][2], af[k2][mt][3]);
            }
#pragma unroll
            for (int k2 = 0; k2 < 2; k2++) {
#pragma unroll
                for (int nt = 0; nt < 4; nt++) {
                    unsigned b0 = bf[k2][nt >> 1][nt & 1];
                    unsigned b1 = bf[k2][nt >> 1][(nt & 1) + 2];
#pragma unroll
                    for (int mt = 0; mt < 4; mt++) {
                        asm volatile(
                            "mma.sync.aligned.m16n8k16.row.col.f32.f16.f16.f32 "
                            "{%0,%1,%2,%3}, {%4,%5,%6,%7}, {%8,%9}, {%0,%1,%2,%3};"
                            : "+f"(acc[mt][nt][0]), "+f"(acc[mt][nt][1]),
                              "+f"(acc[mt][nt][2]), "+f"(acc[mt][nt][3])
                            : "r"(af[k2][mt][0]), "r"(af[k2][mt][1]),
                              "r"(af[k2][mt][2]), "r"(af[k2][mt][3]),
                              "r"(b0), "r"(b1));
                    }
                }
            }
        }
    }

    // ---- epilogue ----
#pragma unroll
    for (int mt = 0; mt < 4; mt++) {
#pragma unroll
        for (int half = 0; half < 2; half++) {
            int rl = warpM * 64 + mt * 16 + rr + 8 * half;
            float ll = __logf(2.0f + (float)(l0 + rl));
            float sumv = 0.f;
#pragma unroll
            for (int nt = 0; nt < 4; nt++) {
#pragma unroll
                for (int j = 0; j < 2; j++) {
                    int col = warpN * 32 + nt * 8 + qa * 2 + j;
                    float sc = acc[mt][nt][half * 2 + j] + eb[col] + ll * eb[TN + col];
#pragma unroll
                    for (int w = 0; w < 5; w++)
                        sc += prevs[rl + w] * eb[(3 + w) * TN + col];
                    sumv += tanh_fast(sc) * eb[2 * TN + col];
                }
            }
            sumv += __shfl_xor_sync(0xffffffffu, sumv, 1);
            sumv += __shfl_xor_sync(0xffffffffu, sumv, 2);
            if (qa == 0) atomicAdd(&g_score[bb * Ln + l0 + rl], sumv);
        }
    }
}

// ---------------------------------------------------------------------------
// Launch 4: per-batch softmax stats (max, 1/sum)
// ---------------------------------------------------------------------------
__global__ void stats_kernel()
{
    int b = blockIdx.x;
    int tid = threadIdx.x;   // 256
    __shared__ float red[256];
    __shared__ float s_max;

    float m = -1e30f;
    for (int l = tid; l < Ln; l += 256) m = fmaxf(m, g_score[b * Ln + l]);
    red[tid] = m;
    __syncthreads();
    for (int s = 128; s > 0; s >>= 1) {
        if (tid < s) red[tid] = fmaxf(red[tid], red[tid + s]);
        __syncthreads();
    }
    if (tid == 0) s_max = red[0];
    __syncthreads();

    float sum = 0.f;
    for (int l = tid; l < Ln; l += 256) sum += __expf(g_score[b * Ln + l] - s_max);
    red[tid] = sum;
    __syncthreads();
    for (int s = 128; s > 0; s >>= 1) {
        if (tid < s) red[tid] += red[tid + s];
        __syncthreads();
    }
    if (tid == 0) {
        g_stat[2 * b] = s_max;
        g_stat[2 * b + 1] = 1.0f / red[0];
    }
}

// ---------------------------------------------------------------------------
// Launch 5: fused attn-write + context accumulate
// ---------------------------------------------------------------------------
__global__ __launch_bounds__(512) void context_kernel(float* __restrict__ out)
{
    int lc = blockIdx.x;    // 16 chunks of 128 rows
    int b  = blockIdx.y;    // 32
    int tid = threadIdx.x;  // 512 half2 cols
    __shared__ float watt[128];

    float smax = g_stat[2 * b], sinv = g_stat[2 * b + 1];
    if (tid < 128) {
        float w = __expf(g_score[b * Ln + lc * 128 + tid] - smax) * sinv;
        watt[tid] = w;
        out[Bn * Dn + b * Ln + lc * 128 + tid] = w;
    }
    __syncthreads();

    const __half2* v = reinterpret_cast<const __half2*>(g_valsh)
                     + ((size_t)b * Ln + (size_t)lc * 128) * (Dn / 2) + tid;
    float ax = 0.f, ay = 0.f;
#pragma unroll 8
    for (int l = 0; l < 128; l++) {
        float2 f = __half22float2(v[(size_t)l * (Dn / 2)]);
        ax += watt[l] * f.x;
        ay += watt[l] * f.y;
    }
    atomicAdd(&out[b * Dn + 2 * tid], ax);
    atomicAdd(&out[b * Dn + 2 * tid + 1], ay);
}

// ---------------------------------------------------------------------------
extern "C" void kernel_launch(void* const* d_in, const int* in_sizes, int n_in,
                              void* d_out, int out_size)
{
    const float* query = (const float*)d_in[0];
    const float* values = (const float*)d_in[1];
    const float* mask = (const float*)d_in[2];
    const float* prev = (const float*)d_in[3];
    const int*   tstep = (const int*)d_in[4];
    const float* Wh = (const float*)d_in[5];
    const float* bh = (const float*)d_in[6];
    const float* Wv = (const float*)d_in[7];
    const float* bv = (const float*)d_in[8];
    const float* Wp = (const float*)d_in[9];
    const float* bp = (const float*)d_in[10];
    const float* Wm = (const float*)d_in[11];
    const float* bm = (const float*)d_in[12];
    const float* vw = (const float*)d_in[13];
    const float* vb = (const float*)d_in[14];
    float* out = (float*)d_out;

    const int smem_bytes = 2 * NST * STAGE_BYTES + (8 * TN + TM + 8) * 4;
    cudaFuncSetAttribute(score_kernel,
                         cudaFuncAttributeMaxDynamicSharedMemorySize, smem_bytes);

    convert_values_kernel<<<((size_t)Bn * Ln * Dn / 8) / 256, 256>>>((const float4*)values);
    misc_kernel<<<(Un * Dn + 255) / 256, 256>>>(Wv, mask, vb, out);
    prep_kernel<<<Bn, 512>>>(query, mask, tstep, Wh, bh, bv, Wp, bp, bm);
    dim3 gs(Un / TN, Ln / TM, Bn);
    score_kernel<<<gs, 256, smem_bytes>>>(Wp, Wm, vw, prev);
    stats_kernel<<<Bn, 256>>>();
    context_kernel<<<dim3(16, Bn), 512>>>(out);
}

// round 12
// speedup vs baseline: 1.2324x; 1.0418x over previous
#include <cuda_runtime.h>
#include <cuda_fp16.h>
#include <math.h>

#define Bn 32
#define Ln 2048
#define Dn 1024
#define Un 512

#define TM 128
#define TN 128
#define KCH 64              // halfs per k-stage (128 B rows)
#define NST 3
#define NSTAGES (Dn / KCH)  // 16
#define STAGE_HALFS (TM * KCH)         // 8192
#define STAGE_BYTES (STAGE_HALFS * 2)  // 16384

// static device scratch (no runtime allocation)
__device__ __align__(16) __half g_valsh[(size_t)Bn * Ln * Dn];  // fp16 values
__device__ __align__(16) __half g_wvTh[Un * Dn];                // fp16 Wv^T [u][k]
__device__ float g_ubias[Bn * Un];
__device__ float g_score[Bn * Ln];
__device__ float g_stat[Bn * 2];

__device__ __forceinline__ float tanh_fast(float x) {
    float y;
    asm("tanh.approx.f32 %0, %1;" : "=f"(y) : "f"(x));
    return y;
}

__device__ __forceinline__ void ldsm4(unsigned addr, unsigned& r0, unsigned& r1,
                                      unsigned& r2, unsigned& r3) {
    asm volatile("ldmatrix.sync.aligned.m8n8.x4.shared.b16 {%0,%1,%2,%3}, [%4];"
                 : "=r"(r0), "=r"(r1), "=r"(r2), "=r"(r3) : "r"(addr));
}

struct Frag {
    unsigned a[4][4];
    unsigned b[2][4];
};

// ---------------------------------------------------------------------------
// Launch 0: values -> fp16 (rn), 8 elems/thread
// ---------------------------------------------------------------------------
__global__ void convert_values_kernel(const float4* __restrict__ src) {
    size_t i = (size_t)blockIdx.x * blockDim.x + threadIdx.x;
    float4 a = src[2 * i], b = src[2 * i + 1];
    union { uint4 u; __half2 h[4]; } o;
    o.h[0] = __floats2half2_rn(a.x, a.y);
    o.h[1] = __floats2half2_rn(a.z, a.w);
    o.h[2] = __floats2half2_rn(b.x, b.y);
    o.h[3] = __floats2half2_rn(b.z, b.w);
    reinterpret_cast<uint4*>(g_valsh)[i] = o.u;
}

// ---------------------------------------------------------------------------
// Launch 1 (fused misc): Wv -> transposed fp16 [u][k]; g_score init;
// zero context output region
// ---------------------------------------------------------------------------
__global__ void misc_kernel(const float* __restrict__ Wv,
                            const float* __restrict__ mask,
                            const float* __restrict__ vb,
                            float* __restrict__ out)
{
    int i = blockIdx.x * blockDim.x + threadIdx.x;
    if (i < Un * Dn) {
        int u = i >> 10, k = i & 1023;
        g_wvTh[i] = __float2half_rn(Wv[k * Un + u]);
    }
    if (i < Bn * Ln) g_score[i] = vb[0] + mask[i] * -1e9f;
    if (i < Bn * Dn) out[i] = 0.0f;
}

// ---------------------------------------------------------------------------
// Launch 2: per-batch prep (q@Wh + fused l-independent bias terms)
// ---------------------------------------------------------------------------
__global__ void prep_kernel(const float* __restrict__ query,
                            const float* __restrict__ mask,
                            const int*   __restrict__ tstep,
                            const float* __restrict__ Wh,
                            const float* __restrict__ bh,
                            const float* __restrict__ bv,
                            const float* __restrict__ Wp,
                            const float* __restrict__ bp,
                            const float* __restrict__ bm)
{
    int b = blockIdx.x;
    int tid = threadIdx.x;                 // 512 threads
    __shared__ float qs[Dn];
    __shared__ float red[512];
    __shared__ float s_loglen, s_logts;

    float cnt = 0.f;
    for (int l = tid; l < Ln; l += 512)
        cnt += (mask[b * Ln + l] == 0.0f) ? 1.0f : 0.0f;
    red[tid] = cnt;
    __syncthreads();
    for (int s = 256; s > 0; s >>= 1) {
        if (tid < s) red[tid] += red[tid + s];
        __syncthreads();
    }
    if (tid == 0) {
        s_loglen = __logf(1.0f + red[0]);
        int iv = tstep[0];
        float ts;
        if (iv >= 0 && iv < 1000000) ts = (float)iv;
        else ts = __int_as_float(iv);
        s_logts = __logf(1.0f + ts);
    }
    for (int d = tid; d < Dn; d += 512) qs[d] = query[b * Dn + d];
    __syncthreads();

    int u = tid;
    float acc = 0.f;
#pragma unroll 8
    for (int d = 0; d < Dn; d++) acc += qs[d] * Wh[d * Un + u];
    g_ubias[b * Un + u] = acc + bh[u] + bv[u] + bp[u] + bm[u]
                        + s_logts * Wp[u] + s_loglen * Wp[2 * Un + u];
}

// ---------------------------------------------------------------------------
// Launch 3 (profiled): fused score GEMM, fp16 m16n8k16, ldmatrix,
//   k16-slice software pipeline (ping-pong frag sets), KCH=64 stages, NST=3.
//   256 thr = 8 warps (2M x 4N); warp tile 64x32; TM=128, TN=128
// ---------------------------------------------------------------------------
__global__ __launch_bounds__(256, 2) void score_kernel(
    const float* __restrict__ Wp,
    const float* __restrict__ Wm,
    const float* __restrict__ vw,
    const float* __restrict__ prev)
{
    extern __shared__ char smraw[];
    __half* As = (__half*)smraw;                       // NST*16KB
    __half* Bs = As + NST * STAGE_HALFS;               // NST*16KB
    float*  eb = (float*)(Bs + NST * STAGE_HALFS);     // 8*TN floats
    float*  prevs = eb + 8 * TN;                       // TM+4
    unsigned As_u = (unsigned)__cvta_generic_to_shared(As);
    unsigned Bs_u = (unsigned)__cvta_generic_to_shared(Bs);

    int utile = blockIdx.x, ltile = blockIdx.y, bb = blockIdx.z;
    int l0 = ltile * TM, u0 = utile * TN;
    int tid = threadIdx.x, lane = tid & 31, warp = tid >> 5;
    int warpM = warp >> 2, warpN = warp & 3;
    int qa = lane & 3, rr = lane >> 2;

    const __half* abase = g_valsh + (size_t)bb * Ln * Dn + (size_t)l0 * Dn;
    const __half* bbase = g_wvTh + (size_t)u0 * Dn;

    // cp.async addressing
    int r0 = tid >> 3, c0 = tid & 7;
    unsigned dst0 = (unsigned)(r0 * 128 + 16 * (c0 ^ (r0 & 7)));
    size_t src0 = (size_t)r0 * Dn + 8 * c0;

    auto issue_stage = [&](int s, unsigned so) {
        const __half* ab = abase + s * KCH;
        const __half* bsrc = bbase + s * KCH;
#pragma unroll
        for (int i = 0; i < 4; i++) {
            asm volatile("cp.async.cg.shared.global [%0], [%1], 16;"
                         ::"r"(As_u + so + dst0 + 4096u * i),
                           "l"(ab + src0 + (size_t)32 * i * Dn));
            asm volatile("cp.async.cg.shared.global [%0], [%1], 16;"
                         ::"r"(Bs_u + so + dst0 + 4096u * i),
                           "l"(bsrc + src0 + (size_t)32 * i * Dn));
        }
    };

    issue_stage(0, 0);
    asm volatile("cp.async.commit_group;");
    issue_stage(1, STAGE_BYTES);
    asm volatile("cp.async.commit_group;");

    // epilogue staging — overlaps first cp.asyncs
    if (tid < TN) {
        eb[tid]          = g_ubias[bb * Un + u0 + tid];
        eb[TN + tid]     = Wp[Un + u0 + tid];
        eb[2 * TN + tid] = vw[u0 + tid];
#pragma unroll
        for (int j = 0; j < 5; j++) eb[(3 + j) * TN + tid] = Wm[j * Un + u0 + tid];
    }
    if (tid < TM + 4) {
        int gl = l0 - 2 + tid;
        prevs[tid] = (gl >= 0 && gl < Ln) ? prev[bb * Ln + gl] : 0.0f;
    }

    // ldmatrix per-lane byte offsets (k16 slice k adds ^ 32*k)
    int lr = lane & 7, grp = lane >> 3;
    int rowadd = lr + 8 * (grp & 1);
    int cbase = grp >> 1;
    unsigned aoffb[4], boffb[2];
#pragma unroll
    for (int mt = 0; mt < 4; mt++) {
        int row = warpM * 64 + mt * 16 + rowadd;
        aoffb[mt] = row * 128 + 16 * (cbase ^ (row & 7));
    }
#pragma unroll
    for (int ntp = 0; ntp < 2; ntp++) {
        int row = warpN * 32 + ntp * 16 + rowadd;
        boffb[ntp] = row * 128 + 16 * (cbase ^ (row & 7));
    }

    auto load_frag = [&](Frag& f, unsigned Ab, unsigned Bb, unsigned x) {
#pragma unroll
        for (int ntp = 0; ntp < 2; ntp++)
            ldsm4(Bb + (boffb[ntp] ^ x),
                  f.b[ntp][0], f.b[ntp][1], f.b[ntp][2], f.b[ntp][3]);
#pragma unroll
        for (int mt = 0; mt < 4; mt++)
            ldsm4(Ab + (aoffb[mt] ^ x),
                  f.a[mt][0], f.a[mt][1], f.a[mt][2], f.a[mt][3]);
    };

    float acc[4][4][4];
#pragma unroll
    for (int a = 0; a < 4; a++)
#pragma unroll
        for (int n = 0; n < 4; n++)
#pragma unroll
            for (int c = 0; c < 4; c++) acc[a][n][c] = 0.f;

    auto mma_frag = [&](const Frag& f) {
#pragma unroll
        for (int nt = 0; nt < 4; nt++) {
            unsigned b0 = f.b[nt >> 1][nt & 1];
            unsigned b1 = f.b[nt >> 1][(nt & 1) + 2];
#pragma unroll
            for (int mt = 0; mt < 4; mt++) {
                asm volatile(
                    "mma.sync.aligned.m16n8k16.row.col.f32.f16.f16.f32 "
                    "{%0,%1,%2,%3}, {%4,%5,%6,%7}, {%8,%9}, {%0,%1,%2,%3};"
                    : "+f"(acc[mt][nt][0]), "+f"(acc[mt][nt][1]),
                      "+f"(acc[mt][nt][2]), "+f"(acc[mt][nt][3])
                    : "r"(f.a[mt][0]), "r"(f.a[mt][1]),
                      "r"(f.a[mt][2]), "r"(f.a[mt][3]),
                      "r"(b0), "r"(b1));
            }
        }
    };

    // ---- k16-slice software pipeline ----
    asm volatile("cp.async.wait_group 1;");
    __syncthreads();

    Frag f0, f1;
    unsigned soC = 0;
    load_frag(f0, As_u, Bs_u, 0);

#pragma unroll 1
    for (int s = 0; s < NSTAGES; s++) {
        unsigned Ac = As_u + soC, Bc = Bs_u + soC;
        load_frag(f1, Ac, Bc, 32);    // k1 loads while k0 MMAs
        mma_frag(f0);
        load_frag(f0, Ac, Bc, 64);    // k2
        mma_frag(f1);
        load_frag(f1, Ac, Bc, 96);    // k3
        mma_frag(f0);
        if (s + 1 < NSTAGES) {
            unsigned soN = soC + STAGE_BYTES;
            if (soN == NST * STAGE_BYTES) soN = 0;
            unsigned soI = soN + STAGE_BYTES;
            if (soI == NST * STAGE_BYTES) soI = 0;
            __syncthreads();
            if (s + 2 < NSTAGES) issue_stage(s + 2, soI);
            asm volatile("cp.async.commit_group;");
            asm volatile("cp.async.wait_group 1;");
            load_frag(f0, As_u + soN, Bs_u + soN, 0);   // next stage k0
            soC = soN;
        }
        mma_frag(f1);
    }

    // ---- epilogue ----
#pragma unroll
    for (int mt = 0; mt < 4; mt++) {
#pragma unroll
        for (int half = 0; half < 2; half++) {
            int rl = warpM * 64 + mt * 16 + rr + 8 * half;
            float ll = __logf(2.0f + (float)(l0 + rl));
            float sumv = 0.f;
#pragma unroll
            for (int nt = 0; nt < 4; nt++) {
#pragma unroll
                for (int j = 0; j < 2; j++) {
                    int col = warpN * 32 + nt * 8 + qa * 2 + j;
                    float sc = acc[mt][nt][half * 2 + j] + eb[col] + ll * eb[TN + col];
#pragma unroll
                    for (int w = 0; w < 5; w++)
                        sc += prevs[rl + w] * eb[(3 + w) * TN + col];
                    sumv += tanh_fast(sc) * eb[2 * TN + col];
                }
            }
            sumv += __shfl_xor_sync(0xffffffffu, sumv, 1);
            sumv += __shfl_xor_sync(0xffffffffu, sumv, 2);
            if (qa == 0) atomicAdd(&g_score[bb * Ln + l0 + rl], sumv);
        }
    }
}

// ---------------------------------------------------------------------------
// Launch 4: per-batch softmax stats (max, 1/sum)
// ---------------------------------------------------------------------------
__global__ void stats_kernel()
{
    int b = blockIdx.x;
    int tid = threadIdx.x;   // 256
    __shared__ float red[256];
    __shared__ float s_max;

    float m = -1e30f;
    for (int l = tid; l < Ln; l += 256) m = fmaxf(m, g_score[b * Ln + l]);
    red[tid] = m;
    __syncthreads();
    for (int s = 128; s > 0; s >>= 1) {
        if (tid < s) red[tid] = fmaxf(red[tid], red[tid + s]);
        __syncthreads();
    }
    if (tid == 0) s_max = red[0];
    __syncthreads();

    float sum = 0.f;
    for (int l = tid; l < Ln; l += 256) sum += __expf(g_score[b * Ln + l] - s_max);
    red[tid] = sum;
    __syncthreads();
    for (int s = 128; s > 0; s >>= 1) {
        if (tid < s) red[tid] += red[tid + s];
        __syncthreads();
    }
    if (tid == 0) {
        g_stat[2 * b] = s_max;
        g_stat[2 * b + 1] = 1.0f / red[0];
    }
}

// ---------------------------------------------------------------------------
// Launch 5: fused attn-write + context accumulate
// ---------------------------------------------------------------------------
__global__ __launch_bounds__(512) void context_kernel(float* __restrict__ out)
{
    int lc = blockIdx.x;    // 16 chunks of 128 rows
    int b  = blockIdx.y;    // 32
    int tid = threadIdx.x;  // 512 half2 cols
    __shared__ float watt[128];

    float smax = g_stat[2 * b], sinv = g_stat[2 * b + 1];
    if (tid < 128) {
        float w = __expf(g_score[b * Ln + lc * 128 + tid] - smax) * sinv;
        watt[tid] = w;
        out[Bn * Dn + b * Ln + lc * 128 + tid] = w;
    }
    __syncthreads();

    const __half2* v = reinterpret_cast<const __half2*>(g_valsh)
                     + ((size_t)b * Ln + (size_t)lc * 128) * (Dn / 2) + tid;
    float ax = 0.f, ay = 0.f;
#pragma unroll 8
    for (int l = 0; l < 128; l++) {
        float2 f = __half22float2(v[(size_t)l * (Dn / 2)]);
        ax += watt[l] * f.x;
        ay += watt[l] * f.y;
    }
    atomicAdd(&out[b * Dn + 2 * tid], ax);
    atomicAdd(&out[b * Dn + 2 * tid + 1], ay);
}

// ---------------------------------------------------------------------------
extern "C" void kernel_launch(void* const* d_in, const int* in_sizes, int n_in,
                              void* d_out, int out_size)
{
    const float* query = (const float*)d_in[0];
    const float* values = (const float*)d_in[1];
    const float* mask = (const float*)d_in[2];
    const float* prev = (const float*)d_in[3];
    const int*   tstep = (const int*)d_in[4];
    const float* Wh = (const float*)d_in[5];
    const float* bh = (const float*)d_in[6];
    const float* Wv = (const float*)d_in[7];
    const float* bv = (const float*)d_in[8];
    const float* Wp = (const float*)d_in[9];
    const float* bp = (const float*)d_in[10];
    const float* Wm = (const float*)d_in[11];
    const float* bm = (const float*)d_in[12];
    const float* vw = (const float*)d_in[13];
    const float* vb = (const float*)d_in[14];
    float* out = (float*)d_out;

    const int smem_bytes = 2 * NST * STAGE_BYTES + (8 * TN + TM + 8) * 4;
    cudaFuncSetAttribute(score_kernel,
                         cudaFuncAttributeMaxDynamicSharedMemorySize, smem_bytes);

    convert_values_kernel<<<((size_t)Bn * Ln * Dn / 8) / 256, 256>>>((const float4*)values);
    misc_kernel<<<(Un * Dn + 255) / 256, 256>>>(Wv, mask, vb, out);
    prep_kernel<<<Bn, 512>>>(query, mask, tstep, Wh, bh, bv, Wp, bp, bm);
    dim3 gs(Un / TN, Ln / TM, Bn);
    score_kernel<<<gs, 256, smem_bytes>>>(Wp, Wm, vw, prev);
    stats_kernel<<<Bn, 256>>>();
    context_kernel<<<dim3(16, Bn), 512>>>(out);
}

// round 15
// speedup vs baseline: 1.2373x; 1.0040x over previous
#include <cuda_runtime.h>
#include <cuda_fp16.h>
#include <math.h>

#define Bn 32
#define Ln 2048
#define Dn 1024
#define Un 512

#define TM 128
#define TN 128
#define KCH 64              // halfs per k-stage (128 B rows)
#define NST 3
#define NSTAGES (Dn / KCH)  // 16
#define STAGE_HALFS (TM * KCH)         // 8192
#define STAGE_BYTES (STAGE_HALFS * 2)  // 16384
#define BOFF (NST * STAGE_BYTES)       // 49152: B ring offset from A ring

// static device scratch (no runtime allocation)
__device__ __align__(16) __half g_valsh[(size_t)Bn * Ln * Dn];  // fp16 values
__device__ __align__(16) __half g_wvTh[Un * Dn];                // fp16 Wv^T [u][k]
__device__ float g_ubias[Bn * Un];
__device__ float g_score[Bn * Ln];
__device__ float g_stat[Bn * 2];

__device__ __forceinline__ float tanh_fast(float x) {
    float y;
    asm("tanh.approx.f32 %0, %1;" : "=f"(y) : "f"(x));
    return y;
}

#define LDSM4(addr, r0_, r1_, r2_, r3_) \
    asm volatile("ldmatrix.sync.aligned.m8n8.x4.shared.b16 {%0,%1,%2,%3}, [%4];" \
                 : "=r"(r0_), "=r"(r1_), "=r"(r2_), "=r"(r3_) : "r"(addr))

#define CPA(dst, src) \
    asm volatile("cp.async.cg.shared.global [%0], [%1], 16;" ::"r"(dst), "l"(src))

// ---------------------------------------------------------------------------
// Launch 0: values -> fp16 (rn), 8 elems/thread
// ---------------------------------------------------------------------------
__global__ void convert_values_kernel(const float4* __restrict__ src) {
    size_t i = (size_t)blockIdx.x * blockDim.x + threadIdx.x;
    float4 a = src[2 * i], b = src[2 * i + 1];
    union { uint4 u; __half2 h[4]; } o;
    o.h[0] = __floats2half2_rn(a.x, a.y);
    o.h[1] = __floats2half2_rn(a.z, a.w);
    o.h[2] = __floats2half2_rn(b.x, b.y);
    o.h[3] = __floats2half2_rn(b.z, b.w);
    reinterpret_cast<uint4*>(g_valsh)[i] = o.u;
}

// ---------------------------------------------------------------------------
// Launch 1 (fused misc): Wv^T fp16; g_score init; out zero
// ---------------------------------------------------------------------------
__global__ void misc_kernel(const float* __restrict__ Wv,
                            const float* __restrict__ mask,
                            const float* __restrict__ vb,
                            float* __restrict__ out)
{
    int i = blockIdx.x * blockDim.x + threadIdx.x;
    if (i < Un * Dn) {
        int u = i >> 10, k = i & 1023;
        g_wvTh[i] = __float2half_rn(Wv[k * Un + u]);
    }
    if (i < Bn * Ln) g_score[i] = vb[0] + mask[i] * -1e9f;
    if (i < Bn * Dn) out[i] = 0.0f;
}

// ---------------------------------------------------------------------------
// Launch 2: per-batch prep (deterministic: one block per batch)
// ---------------------------------------------------------------------------
__global__ void prep_kernel(const float* __restrict__ query,
                            const float* __restrict__ mask,
                            const int*   __restrict__ tstep,
                            const float* __restrict__ Wh,
                            const float* __restrict__ bh,
                            const float* __restrict__ bv,
                            const float* __restrict__ Wp,
                            const float* __restrict__ bp,
                            const float* __restrict__ bm)
{
    int b = blockIdx.x;
    int tid = threadIdx.x;                 // 512 threads
    __shared__ float qs[Dn];
    __shared__ float red[512];
    __shared__ float s_loglen, s_logts;

    float cnt = 0.f;
    for (int l = tid; l < Ln; l += 512)
        cnt += (mask[b * Ln + l] == 0.0f) ? 1.0f : 0.0f;
    red[tid] = cnt;
    __syncthreads();
    for (int s = 256; s > 0; s >>= 1) {
        if (tid < s) red[tid] += red[tid + s];
        __syncthreads();
    }
    if (tid == 0) {
        s_loglen = __logf(1.0f + red[0]);
        int iv = tstep[0];
        float ts;
        if (iv >= 0 && iv < 1000000) ts = (float)iv;
        else ts = __int_as_float(iv);
        s_logts = __logf(1.0f + ts);
    }
    for (int d = tid; d < Dn; d += 512) qs[d] = query[b * Dn + d];
    __syncthreads();

    int u = tid;
    float acc = 0.f;
#pragma unroll 8
    for (int d = 0; d < Dn; d++) acc += qs[d] * Wh[d * Un + u];
    g_ubias[b * Un + u] = acc + bh[u] + bv[u] + bp[u] + bm[u]
                        + s_logts * Wp[u] + s_loglen * Wp[2 * Un + u];
}

// ---------------------------------------------------------------------------
// Launch 3 (profiled): fused score GEMM, fp16 m16n8k16, ldmatrix,
//   k16-slice software pipeline (race-fixed), register-dieted.
//   256 thr = 8 warps (2M x 4N); warp tile 64x32; TM=128, TN=128
// ---------------------------------------------------------------------------
__global__ __launch_bounds__(256, 2) void score_kernel(
    const float* __restrict__ Wp,
    const float* __restrict__ Wm,
    const float* __restrict__ vw,
    const float* __restrict__ prev)
{
    extern __shared__ char smraw[];
    float* eb    = (float*)(smraw + 2 * BOFF);
    float* prevs = eb + 8 * TN;
    unsigned As_u = (unsigned)__cvta_generic_to_shared(smraw);

    int tid = threadIdx.x, lane = tid & 31, warp = tid >> 5;
    int bb = blockIdx.z;
    int l0 = blockIdx.y * TM, u0 = blockIdx.x * TN;

    // cp.async addressing: one dst reg, two advancing src pointers
    int r0 = tid >> 3, c0 = tid & 7;
    unsigned dst0 = (unsigned)(r0 * 128 + 16 * (c0 ^ (r0 & 7)));
    const __half* srcA = g_valsh + (size_t)bb * Ln * Dn + (size_t)l0 * Dn
                       + (size_t)r0 * Dn + 8 * c0;
    const __half* srcB = g_wvTh + (size_t)u0 * Dn + (size_t)r0 * Dn + 8 * c0;

#define ISSUE(bufA) do { \
    _Pragma("unroll") \
    for (int i_ = 0; i_ < 4; i_++) { \
        CPA((bufA) + dst0 + 4096u * i_, srcA + (size_t)32 * i_ * Dn); \
        CPA((bufA) + BOFF + dst0 + 4096u * i_, srcB + (size_t)32 * i_ * Dn); \
    } } while (0)

    ISSUE(As_u);
    srcA += KCH; srcB += KCH;
    asm volatile("cp.async.commit_group;");
    ISSUE(As_u + STAGE_BYTES);
    srcA += KCH; srcB += KCH;
    asm volatile("cp.async.commit_group;");

    // epilogue staging — overlaps first cp.asyncs
    if (tid < TN) {
        eb[tid]          = g_ubias[bb * Un + u0 + tid];
        eb[TN + tid]     = Wp[Un + u0 + tid];
        eb[2 * TN + tid] = vw[u0 + tid];
#pragma unroll
        for (int j = 0; j < 5; j++) eb[(3 + j) * TN + tid] = Wm[j * Un + u0 + tid];
    }
    if (tid < TM + 4) {
        int gl = l0 - 2 + tid;
        prevs[tid] = (gl >= 0 && gl < Ln) ? prev[bb * Ln + gl] : 0.0f;
    }

    // ldmatrix base byte offsets (A mt: +2048*mt; B ntp: +2048*ntp; slice: ^32k)
    int lr = lane & 7, grp = lane >> 3;
    int rowadd = lr + 8 * (grp & 1);
    int cbase = grp >> 1;
    unsigned aoff0, boff0;
    {
        int rowA = (warp >> 2) * 64 + rowadd;
        aoff0 = (unsigned)(rowA * 128 + 16 * (cbase ^ (rowA & 7)));
        int rowB = (warp & 3) * 32 + rowadd;
        boff0 = (unsigned)(rowB * 128 + 16 * (cbase ^ (rowB & 7)));
    }

#define LOADF(fa, fb, buf, x) do { \
    LDSM4((buf) + BOFF + ((boff0 ^ (x))),          fb[0], fb[1], fb[2], fb[3]); \
    LDSM4((buf) + BOFF + ((boff0 ^ (x)) + 2048u),  fb[4], fb[5], fb[6], fb[7]); \
    LDSM4((buf) + (aoff0 ^ (x)),                   fa[0], fa[1], fa[2], fa[3]); \
    LDSM4((buf) + ((aoff0 ^ (x)) + 2048u),         fa[4], fa[5], fa[6], fa[7]); \
    LDSM4((buf) + ((aoff0 ^ (x)) + 4096u),         fa[8], fa[9], fa[10], fa[11]); \
    LDSM4((buf) + ((aoff0 ^ (x)) + 6144u),         fa[12], fa[13], fa[14], fa[15]); \
    } while (0)

    float acc[4][4][4];
#pragma unroll
    for (int a = 0; a < 4; a++)
#pragma unroll
        for (int n = 0; n < 4; n++)
#pragma unroll
            for (int c = 0; c < 4; c++) acc[a][n][c] = 0.f;

#define MMAF(fa, fb) do { \
    _Pragma("unroll") \
    for (int nt_ = 0; nt_ < 4; nt_++) { \
        unsigned b0_ = fb[(nt_ >> 1) * 4 + (nt_ & 1)]; \
        unsigned b1_ = fb[(nt_ >> 1) * 4 + (nt_ & 1) + 2]; \
        _Pragma("unroll") \
        for (int mt_ = 0; mt_ < 4; mt_++) { \
            asm volatile( \
                "mma.sync.aligned.m16n8k16.row.col.f32.f16.f16.f32 " \
                "{%0,%1,%2,%3}, {%4,%5,%6,%7}, {%8,%9}, {%0,%1,%2,%3};" \
                : "+f"(acc[mt_][nt_][0]), "+f"(acc[mt_][nt_][1]), \
                  "+f"(acc[mt_][nt_][2]), "+f"(acc[mt_][nt_][3]) \
                : "r"(fa[mt_ * 4]), "r"(fa[mt_ * 4 + 1]), \
                  "r"(fa[mt_ * 4 + 2]), "r"(fa[mt_ * 4 + 3]), \
                  "r"(b0_), "r"(b1_)); \
        } } } while (0)

    unsigned f0a[16], f0b[8], f1a[16], f1b[8];

    // stage 0 ready: own-wait THEN barrier (all threads' copies visible)
    asm volatile("cp.async.wait_group 1;");
    __syncthreads();

    unsigned bufC = As_u;
    LOADF(f0a, f0b, bufC, 0u);

#pragma unroll 1
    for (int s = 0; s < NSTAGES; s++) {
        LOADF(f1a, f1b, bufC, 32u);
        MMAF(f0a, f0b);
        LOADF(f0a, f0b, bufC, 64u);
        MMAF(f1a, f1b);
        LOADF(f1a, f1b, bufC, 96u);
        MMAF(f0a, f0b);
        if (s + 1 < NSTAGES) {
            unsigned bufI = (bufC == As_u) ? As_u + 2 * STAGE_BYTES
                                           : bufC - STAGE_BYTES;
            unsigned bufN = (bufC == As_u + 2 * STAGE_BYTES) ? As_u
                                                             : bufC + STAGE_BYTES;
            // RACE FIX: issue prefetch, commit, wait own group, THEN barrier,
            // THEN read the next stage (other threads' copies now visible).
            // bufI reuse is safe: its last reads preceded the previous
            // iteration's barrier.
            if (s + 2 < NSTAGES) {
                ISSUE(bufI);
                srcA += KCH; srcB += KCH;
            }
            asm volatile("cp.async.commit_group;");
            asm volatile("cp.async.wait_group 1;");
            __syncthreads();
            LOADF(f0a, f0b, bufN, 0u);
            bufC = bufN;
        }
        MMAF(f1a, f1b);
    }

    // ---- epilogue ----
    int qa = lane & 3, rr = lane >> 2;
    int warpM = warp >> 2, warpN = warp & 3;
#pragma unroll
    for (int mt = 0; mt < 4; mt++) {
#pragma unroll
        for (int half = 0; half < 2; half++) {
            int rl = warpM * 64 + mt * 16 + rr + 8 * half;
            float ll = __logf(2.0f + (float)(l0 + rl));
            float sumv = 0.f;
#pragma unroll
            for (int nt = 0; nt < 4; nt++) {
#pragma unroll
                for (int j = 0; j < 2; j++) {
                    int col = warpN * 32 + nt * 8 + qa * 2 + j;
                    float sc = acc[mt][nt][half * 2 + j] + eb[col] + ll * eb[TN + col];
#pragma unroll
                    for (int w = 0; w < 5; w++)
                        sc += prevs[rl + w] * eb[(3 + w) * TN + col];
                    sumv += tanh_fast(sc) * eb[2 * TN + col];
                }
            }
            sumv += __shfl_xor_sync(0xffffffffu, sumv, 1);
            sumv += __shfl_xor_sync(0xffffffffu, sumv, 2);
            if (qa == 0) atomicAdd(&g_score[bb * Ln + l0 + rl], sumv);
        }
    }
}

// ---------------------------------------------------------------------------
// Launch 4: per-batch softmax stats (max, 1/sum)
// ---------------------------------------------------------------------------
__global__ __launch_bounds__(1024) void stats_kernel()
{
    int b = blockIdx.x;
    int tid = threadIdx.x;   // 1024
    __shared__ float red[1024];
    __shared__ float s_max;

    float m = fmaxf(g_score[b * Ln + tid], g_score[b * Ln + 1024 + tid]);
    red[tid] = m;
    __syncthreads();
    for (int s = 512; s > 0; s >>= 1) {
        if (tid < s) red[tid] = fmaxf(red[tid], red[tid + s]);
        __syncthreads();
    }
    if (tid == 0) s_max = red[0];
    __syncthreads();

    float sum = __expf(g_score[b * Ln + tid] - s_max)
              + __expf(g_score[b * Ln + 1024 + tid] - s_max);
    red[tid] = sum;
    __syncthreads();
    for (int s = 512; s > 0; s >>= 1) {
        if (tid < s) red[tid] += red[tid + s];
        __syncthreads();
    }
    if (tid == 0) {
        g_stat[2 * b] = s_max;
        g_stat[2 * b + 1] = 1.0f / red[0];
    }
}

// ---------------------------------------------------------------------------
// Launch 5: fused attn-write + context accumulate
// ---------------------------------------------------------------------------
__global__ __launch_bounds__(512) void context_kernel(float* __restrict__ out)
{
    int lc = blockIdx.x;    // 16 chunks of 128 rows
    int b  = blockIdx.y;    // 32
    int tid = threadIdx.x;  // 512 half2 cols
    __shared__ float watt[128];

    float smax = g_stat[2 * b], sinv = g_stat[2 * b + 1];
    if (tid < 128) {
        float w = __expf(g_score[b * Ln + lc * 128 + tid] - smax) * sinv;
        watt[tid] = w;
        out[Bn * Dn + b * Ln + lc * 128 + tid] = w;
    }
    __syncthreads();

    const __half2* v = reinterpret_cast<const __half2*>(g_valsh)
                     + ((size_t)b * Ln + (size_t)lc * 128) * (Dn / 2) + tid;
    float ax = 0.f, ay = 0.f;
#pragma unroll 8
    for (int l = 0; l < 128; l++) {
        float2 f = __half22float2(v[(size_t)l * (Dn / 2)]);
        ax += watt[l] * f.x;
        ay += watt[l] * f.y;
    }
    atomicAdd(&out[b * Dn + 2 * tid], ax);
    atomicAdd(&out[b * Dn + 2 * tid + 1], ay);
}

// ---------------------------------------------------------------------------
extern "C" void kernel_launch(void* const* d_in, const int* in_sizes, int n_in,
                              void* d_out, int out_size)
{
    const float* query = (const float*)d_in[0];
    const float* values = (const float*)d_in[1];
    const float* mask = (const float*)d_in[2];
    const float* prev = (const float*)d_in[3];
    const int*   tstep = (const int*)d_in[4];
    const float* Wh = (const float*)d_in[5];
    const float* bh = (const float*)d_in[6];
    const float* Wv = (const float*)d_in[7];
    const float* bv = (const float*)d_in[8];
    const float* Wp = (const float*)d_in[9];
    const float* bp = (const float*)d_in[10];
    const float* Wm = (const float*)d_in[11];
    const float* bm = (const float*)d_in[12];
    const float* vw = (const float*)d_in[13];
    const float* vb = (const float*)d_in[14];
    float* out = (float*)d_out;

    const int smem_bytes = 2 * BOFF + (8 * TN + TM + 8) * 4;
    cudaFuncSetAttribute(score_kernel,
                         cudaFuncAttributeMaxDynamicSharedMemorySize, smem_bytes);

    convert_values_kernel<<<((size_t)Bn * Ln * Dn / 8) / 256, 256>>>((const float4*)values);
    misc_kernel<<<(Un * Dn + 255) / 256, 256>>>(Wv, mask, vb, out);
    prep_kernel<<<Bn, 512>>>(query, mask, tstep, Wh, bh, bv, Wp, bp, bm);
    dim3 gs(Un / TN, Ln / TM, Bn);
    score_kernel<<<gs, 256, smem_bytes>>>(Wp, Wm, vw, prev);
    stats_kernel<<<Bn, 1024>>>();
    context_kernel<<<dim3(16, Bn), 512>>>(out);
}